// round 12
// baseline (speedup 1.0000x reference)
#include <cuda_runtime.h>
#include <cuda_bf16.h>
#include <cstdint>
#include <cstddef>

typedef unsigned long long ull;

#define BB 512
#define TT 1024
#define INDIM 32
#define HH 128
#define GG 512            // 4*H
#define DLL 256
#define OUTD 32
#define M_TOT (BB*TT)     // 524288

// ---- lstm smem layout (round-4/7, proven — FROZEN) ----
#define KPSM 48
#define LSTM_SMEM ((49152 + 512 + 6144) * 4)    // 223232 bytes

#define CST 68                                  // staged C row stride (272B, 16B-aligned)
#define CSTAGE_BYTES (128 * CST * 4)            // 34816

// -------- device scratch (static; no runtime allocation) --------
__device__ float g_xg[(size_t)M_TOT * GG];
__device__ float g_h0[(size_t)M_TOT * HH];
__device__ float g_hlast[BB * HH];
__device__ float g_WT0[HH * GG];
__device__ float g_WT1[HH * GG];

// ---------------- f32x2 helpers (lstm) ----------------
__device__ __forceinline__ ull fma2(ull a, ull b, ull c) {
    ull d;
    asm("fma.rn.f32x2 %0, %1, %2, %3;" : "=l"(d) : "l"(a), "l"(b), "l"(c));
    return d;
}
__device__ __forceinline__ void unpack2(ull v, float& x, float& y) {
    unsigned a, b;
    asm("mov.b64 {%0, %1}, %2;" : "=r"(a), "=r"(b) : "l"(v));
    x = __uint_as_float(a);
    y = __uint_as_float(b);
}
__device__ __forceinline__ float red2(ull v) {
    float a, b;
    unpack2(v, a, b);
    return a + b;
}
__device__ __forceinline__ float sigf(float x)  { return __fdividef(1.0f, 1.0f + __expf(-x)); }
__device__ __forceinline__ float tanhx(float x) { return __fdividef(2.0f, 1.0f + __expf(-2.0f * x)) - 1.0f; }

// -------- interleave Whh for lstm (unchanged) --------
__global__ void prep_whh(const float* __restrict__ W, float* __restrict__ WTI) {
    int idx = blockIdx.x * 256 + threadIdx.x;
    if (idx < HH * GG) {
        int r = idx >> 15;
        int rem = idx & 32767;
        int kp = rem >> 9;
        int rem2 = rem & 511;
        int j = rem2 >> 2;
        int t = rem2 & 3;
        int qq = t >> 1;
        int e = t & 1;
        int q = r * 2 + qq;
        WTI[idx] = W[(q * HH + j) * HH + 2 * kp + e];
    }
}

// ================= mma.sync bf16 hi/lo pre-gate GEMM =================
// C[m][n] = sum_k A[m][k]*W[n][k] + ba[n] + bb[n]
// grid (M/128): A tile converted once per CTA; 8 N-blocks of 64 rows of W;
// 2 CTAs/SM. 8 warps: warp tile 32m x 32n. 3-MMA split: Ahi*Whi+Alo*Whi+Ahi*Wlo.
// Epilogue stages C block (bias added) into the W smem region (stride 68,
// 16B-aligned rows), then issues fully-coalesced float4 row stores.

#define MMA_BF16(D, A0, A1, A2, A3, B0, B1) \
    asm volatile( \
        "mma.sync.aligned.m16n8k16.row.col.f32.bf16.bf16.f32 " \
        "{%0,%1,%2,%3}, {%4,%5,%6,%7}, {%8,%9}, {%0,%1,%2,%3};" \
        : "+f"((D)[0]), "+f"((D)[1]), "+f"((D)[2]), "+f"((D)[3]) \
        : "r"(A0), "r"(A1), "r"(A2), "r"(A3), "r"(B0), "r"(B1))

__device__ __forceinline__ void cvt_hilo(float4 v, uint2& oh, uint2& ol) {
    __nv_bfloat162 h01 = __floats2bfloat162_rn(v.x, v.y);
    __nv_bfloat162 h23 = __floats2bfloat162_rn(v.z, v.w);
    __nv_bfloat162 l01 = __floats2bfloat162_rn(v.x - __bfloat162float(h01.x),
                                               v.y - __bfloat162float(h01.y));
    __nv_bfloat162 l23 = __floats2bfloat162_rn(v.z - __bfloat162float(h23.x),
                                               v.w - __bfloat162float(h23.y));
    oh.x = *(uint32_t*)&h01; oh.y = *(uint32_t*)&h23;
    ol.x = *(uint32_t*)&l01; ol.y = *(uint32_t*)&l23;
}

__global__ void __launch_bounds__(256, 2) mma_pregate(
    const float* __restrict__ A,     // [M][K] fp32
    const float* __restrict__ W,     // [512][K] fp32
    const float* __restrict__ ba, const float* __restrict__ bb,
    float* __restrict__ C,           // [M][512]
    int K)
{
    extern __shared__ __nv_bfloat16 smem[];
    const int stride = K + 8;
    const int abytes = 2 * 128 * stride * 2;         // A hi+lo
    const int wbytes = 2 * 64 * stride * 2;          // W hi+lo
    const int ubytes = (wbytes > CSTAGE_BYTES) ? wbytes : CSTAGE_BYTES;

    __nv_bfloat16* sAhi = smem;
    __nv_bfloat16* sAlo = sAhi + 128 * stride;
    __nv_bfloat16* sWhi = sAlo + 128 * stride;       // union start
    __nv_bfloat16* sWlo = sWhi + 64 * stride;
    float* sCst = (float*)sWhi;                      // staged C (reuses W region)
    float* sbias = (float*)((char*)smem + abytes + ubytes);

    const int tid = threadIdx.x;
    const int lane = tid & 31;
    const int wid = tid >> 5;
    const int wm = wid & 3;              // warp m index: rows wm*32 .. +32
    const int wn = wid >> 2;             // warp n index: cols wn*32 .. +32
    const int g = lane >> 2;
    const int tig = lane & 3;

    const int m0 = blockIdx.x * 128;
    const int kv = K >> 2;

    for (int i = tid; i < 512; i += 256) sbias[i] = ba[i] + bb[i];

    // convert A tile once: 128 rows x K
    for (int idx = tid; idx < 128 * kv; idx += 256) {
        int row = idx / kv;
        int q = idx - row * kv;
        float4 v = *(const float4*)(A + (size_t)(m0 + row) * K + q * 4);
        uint2 oh, ol;
        cvt_hilo(v, oh, ol);
        *(uint2*)(&sAhi[row * stride + q * 4]) = oh;
        *(uint2*)(&sAlo[row * stride + q * 4]) = ol;
    }

    for (int nb = 0; nb < 8; nb++) {
        __syncthreads();   // prior stage-stores done reading sCst; A ready at nb=0
        // convert W block: rows nb*64 .. +64
        for (int idx = tid; idx < 64 * kv; idx += 256) {
            int row = idx / kv;
            int q = idx - row * kv;
            float4 v = *(const float4*)(W + (size_t)(nb * 64 + row) * K + q * 4);
            uint2 oh, ol;
            cvt_hilo(v, oh, ol);
            *(uint2*)(&sWhi[row * stride + q * 4]) = oh;
            *(uint2*)(&sWlo[row * stride + q * 4]) = ol;
        }
        __syncthreads();

        float d[2][4][4];
        #pragma unroll
        for (int mf = 0; mf < 2; mf++)
            #pragma unroll
            for (int nf = 0; nf < 4; nf++)
                #pragma unroll
                for (int e = 0; e < 4; e++) d[mf][nf][e] = 0.0f;

        const int nks = K >> 4;
        for (int ks = 0; ks < nks; ks++) {
            const int c0 = ks * 16 + 2 * tig;
            const int c1 = c0 + 8;

            uint32_t AH[2][4], AL[2][4];
            #pragma unroll
            for (int mf = 0; mf < 2; mf++) {
                int r0 = (wm * 32 + mf * 16 + g) * stride;
                int r8 = r0 + 8 * stride;
                AH[mf][0] = *(const uint32_t*)(&sAhi[r0 + c0]);
                AH[mf][1] = *(const uint32_t*)(&sAhi[r8 + c0]);
                AH[mf][2] = *(const uint32_t*)(&sAhi[r0 + c1]);
                AH[mf][3] = *(const uint32_t*)(&sAhi[r8 + c1]);
                AL[mf][0] = *(const uint32_t*)(&sAlo[r0 + c0]);
                AL[mf][1] = *(const uint32_t*)(&sAlo[r8 + c0]);
                AL[mf][2] = *(const uint32_t*)(&sAlo[r0 + c1]);
                AL[mf][3] = *(const uint32_t*)(&sAlo[r8 + c1]);
            }
            #pragma unroll
            for (int nf = 0; nf < 4; nf++) {
                int rb = (wn * 32 + nf * 8 + g) * stride;
                uint32_t BH0 = *(const uint32_t*)(&sWhi[rb + c0]);
                uint32_t BH1 = *(const uint32_t*)(&sWhi[rb + c1]);
                uint32_t BL0 = *(const uint32_t*)(&sWlo[rb + c0]);
                uint32_t BL1 = *(const uint32_t*)(&sWlo[rb + c1]);
                #pragma unroll
                for (int mf = 0; mf < 2; mf++) {
                    MMA_BF16(d[mf][nf], AH[mf][0], AH[mf][1], AH[mf][2], AH[mf][3], BH0, BH1);
                    MMA_BF16(d[mf][nf], AL[mf][0], AL[mf][1], AL[mf][2], AL[mf][3], BH0, BH1);
                    MMA_BF16(d[mf][nf], AH[mf][0], AH[mf][1], AH[mf][2], AH[mf][3], BL0, BL1);
                }
            }
        }

        // stage C block (bias added) into reused W region
        __syncthreads();   // all warps done reading W for this nb
        #pragma unroll
        for (int mf = 0; mf < 2; mf++) {
            int r0 = wm * 32 + mf * 16 + g;
            #pragma unroll
            for (int nf = 0; nf < 4; nf++) {
                int cl = wn * 32 + nf * 8 + 2 * tig;
                float bx = sbias[nb * 64 + cl];
                float by = sbias[nb * 64 + cl + 1];
                float2 v0, v1;
                v0.x = d[mf][nf][0] + bx; v0.y = d[mf][nf][1] + by;
                v1.x = d[mf][nf][2] + bx; v1.y = d[mf][nf][3] + by;
                *(float2*)(&sCst[r0 * CST + cl]) = v0;
                *(float2*)(&sCst[(r0 + 8) * CST + cl]) = v1;
            }
        }
        __syncthreads();
        // coalesced store: 128 rows x 16 float4 (each warp = 2 full 256B rows)
        #pragma unroll
        for (int i = 0; i < 8; i++) {
            int idx = tid + i * 256;
            int row = idx >> 4;
            int c4 = (idx & 15) << 2;
            float4 v = *(const float4*)(&sCst[row * CST + c4]);
            *(float4*)(C + (size_t)(m0 + row) * GG + nb * 64 + c4) = v;
        }
    }
}

// -------- LSTM recurrence (round-4/7, proven — FROZEN) --------
#define MAC4(HV0, HV1, HV2, HV3, W0, W1) { \
    a00 = fma2(HV0, W0.x, a00); a01 = fma2(HV0, W0.y, a01); \
    a02 = fma2(HV0, W1.x, a02); a03 = fma2(HV0, W1.y, a03); \
    a10 = fma2(HV1, W0.x, a10); a11 = fma2(HV1, W0.y, a11); \
    a12 = fma2(HV1, W1.x, a12); a13 = fma2(HV1, W1.y, a13); \
    a20 = fma2(HV2, W0.x, a20); a21 = fma2(HV2, W0.y, a21); \
    a22 = fma2(HV2, W1.x, a22); a23 = fma2(HV2, W1.y, a23); \
    a30 = fma2(HV3, W0.x, a30); a31 = fma2(HV3, W0.y, a31); \
    a32 = fma2(HV3, W1.x, a32); a33 = fma2(HV3, W1.y, a33); }

__global__ void __launch_bounds__(512, 1) lstm_layer_kernel(
    const float* __restrict__ xg,
    const float* __restrict__ WTI,
    float* __restrict__ hout,
    float* __restrict__ hlast)
{
    extern __shared__ float sm[];
    const ulonglong2* swA = (const ulonglong2*)sm;
    const ulonglong2* swB = swA + 6144;
    float* sh = sm + 49152;
    float4* sxf = (float4*)(sm + 49152 + 512);

    const int tid = threadIdx.x;
    const int j = tid & 127;
    const int u = tid >> 7;
    const int b0 = blockIdx.x * 4;

    {
        const float4* g4 = (const float4*)WTI;
        float4* s4 = (float4*)sm;
        #pragma unroll 4
        for (int i = tid; i < 6144; i += 512) s4[i] = g4[i];
        #pragma unroll 4
        for (int i = tid; i < 6144; i += 512) s4[6144 + i] = g4[8192 + i];
    }
    ulonglong2 wtA[4], wtB[4];
    {
        const ulonglong2* gA = (const ulonglong2*)WTI;
        const ulonglong2* gB = gA + 8192;
        int kt = KPSM + u * 4;
        #pragma unroll
        for (int i = 0; i < 4; i++) {
            wtA[i] = gA[(size_t)(kt + i) * 128 + j];
            wtB[i] = gB[(size_t)(kt + i) * 128 + j];
        }
    }
    sh[tid] = 0.0f;

    const int klo = u * 24;
    const int kplo = u * 12;

    const size_t xbase = ((size_t)(b0 + u)) * TT * GG + j;
    float* houtP = hout ? hout + ((size_t)(b0 + u)) * TT * HH + j : (float*)0;

    float xc0 = xg[xbase], xc1 = xg[xbase + 128], xc2 = xg[xbase + 256], xc3 = xg[xbase + 384];

    float cc = 0.0f, hh = 0.0f;
    __syncthreads();

    for (int t = 0; t < TT; t++) {
        ull a00 = 0, a01 = 0, a02 = 0, a03 = 0;
        ull a10 = 0, a11 = 0, a12 = 0, a13 = 0;
        ull a20 = 0, a21 = 0, a22 = 0, a23 = 0;
        ull a30 = 0, a31 = 0, a32 = 0, a33 = 0;

        float xn0 = 0, xn1 = 0, xn2 = 0, xn3 = 0;
        if (t + 1 < TT) {
            size_t o = xbase + (size_t)(t + 1) * GG;
            xn0 = xg[o]; xn1 = xg[o + 128]; xn2 = xg[o + 256]; xn3 = xg[o + 384];
        }

        #pragma unroll
        for (int g = 0; g < 6; g++) {
            int kb = klo + g * 4;
            ulonglong2 H0 = *(const ulonglong2*)(sh + kb);
            ulonglong2 H1 = *(const ulonglong2*)(sh + 128 + kb);
            ulonglong2 H2 = *(const ulonglong2*)(sh + 256 + kb);
            ulonglong2 H3 = *(const ulonglong2*)(sh + 384 + kb);
            int kpi = (kplo + g * 2) * 128 + j;
            ulonglong2 w0 = swA[kpi];
            ulonglong2 w1 = swB[kpi];
            MAC4(H0.x, H1.x, H2.x, H3.x, w0, w1);
            ulonglong2 w2 = swA[kpi + 128];
            ulonglong2 w3 = swB[kpi + 128];
            MAC4(H0.y, H1.y, H2.y, H3.y, w2, w3);
        }
        #pragma unroll
        for (int g = 0; g < 2; g++) {
            int kb = 96 + u * 8 + g * 4;
            ulonglong2 H0 = *(const ulonglong2*)(sh + kb);
            ulonglong2 H1 = *(const ulonglong2*)(sh + 128 + kb);
            ulonglong2 H2 = *(const ulonglong2*)(sh + 256 + kb);
            ulonglong2 H3 = *(const ulonglong2*)(sh + 384 + kb);
            MAC4(H0.x, H1.x, H2.x, H3.x, wtA[g * 2], wtB[g * 2]);
            MAC4(H0.y, H1.y, H2.y, H3.y, wtA[g * 2 + 1], wtB[g * 2 + 1]);
        }

        float4 s0, s1, s2, s3;
        s0.x = red2(a00); s0.y = red2(a01); s0.z = red2(a02); s0.w = red2(a03);
        s1.x = red2(a10); s1.y = red2(a11); s1.z = red2(a12); s1.w = red2(a13);
        s2.x = red2(a20); s2.y = red2(a21); s2.z = red2(a22); s2.w = red2(a23);
        s3.x = red2(a30); s3.y = red2(a31); s3.z = red2(a32); s3.w = red2(a33);

        if (u != 0) sxf[(0 * 3 + (u - 1)) * 128 + j] = s0;
        if (u != 1) sxf[(1 * 3 + ((u == 0) ? 0 : u - 1)) * 128 + j] = s1;
        if (u != 2) sxf[(2 * 3 + ((u == 3) ? 2 : u)) * 128 + j] = s2;
        if (u != 3) sxf[(3 * 3 + u) * 128 + j] = s3;
        __syncthreads();
        {
            float4 own = (u == 0) ? s0 : (u == 1) ? s1 : (u == 2) ? s2 : s3;
            float4 p0 = sxf[u * 384 + j];
            float4 p1 = sxf[u * 384 + 128 + j];
            float4 p2 = sxf[u * 384 + 256 + j];
            float gi = own.x + xc0 + p0.x + p1.x + p2.x;
            float gf = own.y + xc1 + p0.y + p1.y + p2.y;
            float gg2 = own.z + xc2 + p0.z + p1.z + p2.z;
            float go = own.w + xc3 + p0.w + p1.w + p2.w;

            float ii = sigf(gi), ff = sigf(gf), g = tanhx(gg2), oo = sigf(go);
            cc = ff * cc + ii * g;
            hh = oo * tanhx(cc);

            sh[u * 128 + j] = hh;
            if (hout) houtP[(size_t)t * HH] = hh;
        }
        xc0 = xn0; xc1 = xn1; xc2 = xn2; xc3 = xn3;
        __syncthreads();
    }

    if (hlast) hlast[(b0 + u) * HH + j] = hh;
}

// -------- MLP head (also zeroes the hidden_init tail: 512*256 = 131072 floats) --------
__device__ __forceinline__ float celuf(float x) { return x > 0.0f ? x : expm1f(x); }

__global__ void __launch_bounds__(256) head_kernel(
    const float* __restrict__ hlast,
    const float* __restrict__ W1, const float* __restrict__ b1,
    const float* __restrict__ W2, const float* __restrict__ b2,
    float* __restrict__ out, int tail_n)
{
    const int b = blockIdx.x;
    const int tid = threadIdx.x;
    __shared__ float sl[HH];
    __shared__ float sy[DLL];

    // zero one tail element per thread (grid*block == tail size)
    int zi = b * 256 + tid;
    if (zi < tail_n) out[BB * OUTD + zi] = 0.0f;

    if (tid < HH) sl[tid] = hlast[b * HH + tid];
    __syncthreads();

    float s = b1[tid];
    const float* w = W1 + (size_t)tid * HH;
    #pragma unroll 8
    for (int k = 0; k < HH; k++) s += sl[k] * w[k];
    sy[tid] = celuf(s);
    __syncthreads();

    if (tid < OUTD) {
        float s2 = b2[tid];
        const float* w2 = W2 + (size_t)tid * DLL;
        #pragma unroll 8
        for (int k = 0; k < DLL; k++) s2 += sy[k] * w2[k];
        out[b * OUTD + tid] = celuf(s2);
    }
}

__global__ void zero_extra(float* __restrict__ p, int n) {
    int i = blockIdx.x * 256 + threadIdx.x;
    if (i < n) p[i] = 0.0f;
}

// -------- launch --------
extern "C" void kernel_launch(void* const* d_in, const int* in_sizes, int n_in,
                              void* d_out, int out_size)
{
    const float* x    = (const float*)d_in[0];
    const float* Wih0 = (const float*)d_in[1];
    const float* Whh0 = (const float*)d_in[2];
    const float* bih0 = (const float*)d_in[3];
    const float* bhh0 = (const float*)d_in[4];
    const float* Wih1 = (const float*)d_in[5];
    const float* Whh1 = (const float*)d_in[6];
    const float* bih1 = (const float*)d_in[7];
    const float* bhh1 = (const float*)d_in[8];
    const float* W1   = (const float*)d_in[9];
    const float* b1   = (const float*)d_in[10];
    const float* W2   = (const float*)d_in[11];
    const float* b2   = (const float*)d_in[12];
    float* out = (float*)d_out;

    float *xgp, *h0p, *hlastp, *wt0p, *wt1p;
    cudaGetSymbolAddress((void**)&xgp,    g_xg);
    cudaGetSymbolAddress((void**)&h0p,    g_h0);
    cudaGetSymbolAddress((void**)&hlastp, g_hlast);
    cudaGetSymbolAddress((void**)&wt0p,   g_WT0);
    cudaGetSymbolAddress((void**)&wt1p,   g_WT1);

    // dynamic smem: A(2x128xstride) + union(W | C-stage) + 512-float bias
    auto smem_for = [](int K) {
        int stride = K + 8;
        int abytes = 2 * 128 * stride * 2;
        int wbytes = 2 * 64 * stride * 2;
        int ubytes = (wbytes > CSTAGE_BYTES) ? wbytes : CSTAGE_BYTES;
        return abytes + ubytes + 512 * 4;
    };
    const int smem_k128 = smem_for(HH);      // 108544
    const int smem_k32  = smem_for(INDIM);   // 57344

    cudaFuncSetAttribute(lstm_layer_kernel, cudaFuncAttributeMaxDynamicSharedMemorySize, LSTM_SMEM);
    cudaFuncSetAttribute(mma_pregate,       cudaFuncAttributeMaxDynamicSharedMemorySize, smem_k128);

    prep_whh<<<256, 256>>>(Whh0, wt0p);
    prep_whh<<<256, 256>>>(Whh1, wt1p);

    // layer 0: pre-gates (mma.sync bf16 split, K=32) then recurrence
    mma_pregate<<<M_TOT / 128, 256, smem_k32>>>(x, Wih0, bih0, bhh0, xgp, INDIM);
    lstm_layer_kernel<<<BB / 4, 512, LSTM_SMEM>>>(xgp, wt0p, h0p, nullptr);

    // layer 1: pre-gates (mma.sync bf16 split, K=128) then recurrence
    mma_pregate<<<M_TOT / 128, 256, smem_k128>>>(h0p, Wih1, bih1, bhh1, xgp, HH);
    lstm_layer_kernel<<<BB / 4, 512, LSTM_SMEM>>>(xgp, wt1p, nullptr, hlastp);

    // head (+tail zeroing; covers exactly 512*256 elements)
    int tail = out_size - BB * OUTD;
    head_kernel<<<BB, 256>>>(hlastp, W1, b1, W2, b2, out, tail);
    // safety: if tail exceeds what head covered (it shouldn't for these shapes)
    int covered = BB * 256;
    if (tail > covered)
        zero_extra<<<(tail - covered + 255) / 256, 256>>>(out + BB * OUTD + covered, tail - covered);
}

// round 13
// speedup vs baseline: 1.6662x; 1.6662x over previous
#include <cuda_runtime.h>
#include <cuda_bf16.h>
#include <cstdint>
#include <cstddef>

typedef unsigned long long ull;

#define BB 512
#define TT 1024
#define INDIM 32
#define HH 128
#define GG 512            // 4*H
#define DLL 256
#define OUTD 32
#define M_TOT (BB*TT)     // 524288

// ---- lstm smem layout (round-4/7, proven — FROZEN) ----
#define KPSM 48
#define LSTM_SMEM ((49152 + 512 + 6144) * 4)    // 223232 bytes

// -------- device scratch (static; no runtime allocation) --------
__device__ float g_xg[(size_t)M_TOT * GG];
__device__ float g_h0[(size_t)M_TOT * HH];
__device__ float g_hlast[BB * HH];
__device__ float g_WT0[HH * GG];
__device__ float g_WT1[HH * GG];

// ---------------- f32x2 helpers (lstm) ----------------
__device__ __forceinline__ ull fma2(ull a, ull b, ull c) {
    ull d;
    asm("fma.rn.f32x2 %0, %1, %2, %3;" : "=l"(d) : "l"(a), "l"(b), "l"(c));
    return d;
}
__device__ __forceinline__ void unpack2(ull v, float& x, float& y) {
    unsigned a, b;
    asm("mov.b64 {%0, %1}, %2;" : "=r"(a), "=r"(b) : "l"(v));
    x = __uint_as_float(a);
    y = __uint_as_float(b);
}
__device__ __forceinline__ float red2(ull v) {
    float a, b;
    unpack2(v, a, b);
    return a + b;
}
__device__ __forceinline__ float sigf(float x)  { return __fdividef(1.0f, 1.0f + __expf(-x)); }
__device__ __forceinline__ float tanhx(float x) { return __fdividef(2.0f, 1.0f + __expf(-2.0f * x)) - 1.0f; }

// -------- interleave Whh for lstm (unchanged) --------
__global__ void prep_whh(const float* __restrict__ W, float* __restrict__ WTI) {
    int idx = blockIdx.x * 256 + threadIdx.x;
    if (idx < HH * GG) {
        int r = idx >> 15;
        int rem = idx & 32767;
        int kp = rem >> 9;
        int rem2 = rem & 511;
        int j = rem2 >> 2;
        int t = rem2 & 3;
        int qq = t >> 1;
        int e = t & 1;
        int q = r * 2 + qq;
        WTI[idx] = W[(q * HH + j) * HH + 2 * kp + e];
    }
}

// ================= mma.sync bf16 hi/lo pre-gate GEMM =================
// C[m][n] = sum_k A[m][k]*W[n][k] + ba[n] + bb[n]
// grid (M/128): A tile converted once per CTA; 8 N-blocks of 64 rows of W,
// smem 104 KB -> 2 CTAs/SM. 8 warps: warp tile 32m x 32n.
// 3-MMA split: Ahi*Whi + Alo*Whi + Ahi*Wlo.

#define MMA_BF16(D, A0, A1, A2, A3, B0, B1) \
    asm volatile( \
        "mma.sync.aligned.m16n8k16.row.col.f32.bf16.bf16.f32 " \
        "{%0,%1,%2,%3}, {%4,%5,%6,%7}, {%8,%9}, {%0,%1,%2,%3};" \
        : "+f"((D)[0]), "+f"((D)[1]), "+f"((D)[2]), "+f"((D)[3]) \
        : "r"(A0), "r"(A1), "r"(A2), "r"(A3), "r"(B0), "r"(B1))

__device__ __forceinline__ void cvt_hilo(float4 v, uint2& oh, uint2& ol) {
    __nv_bfloat162 h01 = __floats2bfloat162_rn(v.x, v.y);
    __nv_bfloat162 h23 = __floats2bfloat162_rn(v.z, v.w);
    __nv_bfloat162 l01 = __floats2bfloat162_rn(v.x - __bfloat162float(h01.x),
                                               v.y - __bfloat162float(h01.y));
    __nv_bfloat162 l23 = __floats2bfloat162_rn(v.z - __bfloat162float(h23.x),
                                               v.w - __bfloat162float(h23.y));
    oh.x = *(uint32_t*)&h01; oh.y = *(uint32_t*)&h23;
    ol.x = *(uint32_t*)&l01; ol.y = *(uint32_t*)&l23;
}

__global__ void __launch_bounds__(256, 2) mma_pregate(
    const float* __restrict__ A,     // [M][K] fp32
    const float* __restrict__ W,     // [512][K] fp32
    const float* __restrict__ ba, const float* __restrict__ bb,
    float* __restrict__ C,           // [M][512]
    int K)
{
    extern __shared__ __nv_bfloat16 smem[];
    const int stride = K + 8;
    __nv_bfloat16* sAhi = smem;
    __nv_bfloat16* sAlo = sAhi + 128 * stride;
    __nv_bfloat16* sWhi = sAlo + 128 * stride;
    __nv_bfloat16* sWlo = sWhi + 64 * stride;
    float* sbias = (float*)(sWlo + 64 * stride);

    const int tid = threadIdx.x;
    const int lane = tid & 31;
    const int wid = tid >> 5;
    const int wm = wid & 3;              // warp m index: rows wm*32 .. +32
    const int wn = wid >> 2;             // warp n index: cols wn*32 .. +32
    const int g = lane >> 2;
    const int tig = lane & 3;

    const int m0 = blockIdx.x * 128;
    const int kv = K >> 2;

    for (int i = tid; i < 512; i += 256) sbias[i] = ba[i] + bb[i];

    // convert A tile once: 128 rows x K
    for (int idx = tid; idx < 128 * kv; idx += 256) {
        int row = idx / kv;
        int q = idx - row * kv;
        float4 v = *(const float4*)(A + (size_t)(m0 + row) * K + q * 4);
        uint2 oh, ol;
        cvt_hilo(v, oh, ol);
        *(uint2*)(&sAhi[row * stride + q * 4]) = oh;
        *(uint2*)(&sAlo[row * stride + q * 4]) = ol;
    }

    for (int nb = 0; nb < 8; nb++) {
        __syncthreads();   // prior mma done reading W (and A ready at nb=0)
        // convert W block: rows nb*64 .. +64
        for (int idx = tid; idx < 64 * kv; idx += 256) {
            int row = idx / kv;
            int q = idx - row * kv;
            float4 v = *(const float4*)(W + (size_t)(nb * 64 + row) * K + q * 4);
            uint2 oh, ol;
            cvt_hilo(v, oh, ol);
            *(uint2*)(&sWhi[row * stride + q * 4]) = oh;
            *(uint2*)(&sWlo[row * stride + q * 4]) = ol;
        }
        __syncthreads();

        float d[2][4][4];
        #pragma unroll
        for (int mf = 0; mf < 2; mf++)
            #pragma unroll
            for (int nf = 0; nf < 4; nf++)
                #pragma unroll
                for (int e = 0; e < 4; e++) d[mf][nf][e] = 0.0f;

        const int nks = K >> 4;
        for (int ks = 0; ks < nks; ks++) {
            const int c0 = ks * 16 + 2 * tig;
            const int c1 = c0 + 8;

            uint32_t AH[2][4], AL[2][4];
            #pragma unroll
            for (int mf = 0; mf < 2; mf++) {
                int r0 = (wm * 32 + mf * 16 + g) * stride;
                int r8 = r0 + 8 * stride;
                AH[mf][0] = *(const uint32_t*)(&sAhi[r0 + c0]);
                AH[mf][1] = *(const uint32_t*)(&sAhi[r8 + c0]);
                AH[mf][2] = *(const uint32_t*)(&sAhi[r0 + c1]);
                AH[mf][3] = *(const uint32_t*)(&sAhi[r8 + c1]);
                AL[mf][0] = *(const uint32_t*)(&sAlo[r0 + c0]);
                AL[mf][1] = *(const uint32_t*)(&sAlo[r8 + c0]);
                AL[mf][2] = *(const uint32_t*)(&sAlo[r0 + c1]);
                AL[mf][3] = *(const uint32_t*)(&sAlo[r8 + c1]);
            }
            #pragma unroll
            for (int nf = 0; nf < 4; nf++) {
                int rb = (wn * 32 + nf * 8 + g) * stride;
                uint32_t BH0 = *(const uint32_t*)(&sWhi[rb + c0]);
                uint32_t BH1 = *(const uint32_t*)(&sWhi[rb + c1]);
                uint32_t BL0 = *(const uint32_t*)(&sWlo[rb + c0]);
                uint32_t BL1 = *(const uint32_t*)(&sWlo[rb + c1]);
                #pragma unroll
                for (int mf = 0; mf < 2; mf++) {
                    MMA_BF16(d[mf][nf], AH[mf][0], AH[mf][1], AH[mf][2], AH[mf][3], BH0, BH1);
                    MMA_BF16(d[mf][nf], AL[mf][0], AL[mf][1], AL[mf][2], AL[mf][3], BH0, BH1);
                    MMA_BF16(d[mf][nf], AH[mf][0], AH[mf][1], AH[mf][2], AH[mf][3], BL0, BL1);
                }
            }
        }

        // epilogue: add bias, store float2 pairs
        #pragma unroll
        for (int mf = 0; mf < 2; mf++) {
            int r0 = wm * 32 + mf * 16 + g;
            #pragma unroll
            for (int nf = 0; nf < 4; nf++) {
                int nl = nb * 64 + wn * 32 + nf * 8 + 2 * tig;
                float bx = sbias[nl];
                float by = sbias[nl + 1];
                float2 o0, o1;
                o0.x = d[mf][nf][0] + bx; o0.y = d[mf][nf][1] + by;
                o1.x = d[mf][nf][2] + bx; o1.y = d[mf][nf][3] + by;
                *(float2*)(C + (size_t)(m0 + r0) * GG + nl) = o0;
                *(float2*)(C + (size_t)(m0 + r0 + 8) * GG + nl) = o1;
            }
        }
    }
}

// -------- LSTM recurrence (round-4/7, proven — FROZEN) --------
#define MAC4(HV0, HV1, HV2, HV3, W0, W1) { \
    a00 = fma2(HV0, W0.x, a00); a01 = fma2(HV0, W0.y, a01); \
    a02 = fma2(HV0, W1.x, a02); a03 = fma2(HV0, W1.y, a03); \
    a10 = fma2(HV1, W0.x, a10); a11 = fma2(HV1, W0.y, a11); \
    a12 = fma2(HV1, W1.x, a12); a13 = fma2(HV1, W1.y, a13); \
    a20 = fma2(HV2, W0.x, a20); a21 = fma2(HV2, W0.y, a21); \
    a22 = fma2(HV2, W1.x, a22); a23 = fma2(HV2, W1.y, a23); \
    a30 = fma2(HV3, W0.x, a30); a31 = fma2(HV3, W0.y, a31); \
    a32 = fma2(HV3, W1.x, a32); a33 = fma2(HV3, W1.y, a33); }

__global__ void __launch_bounds__(512, 1) lstm_layer_kernel(
    const float* __restrict__ xg,
    const float* __restrict__ WTI,
    float* __restrict__ hout,
    float* __restrict__ hlast)
{
    extern __shared__ float sm[];
    const ulonglong2* swA = (const ulonglong2*)sm;
    const ulonglong2* swB = swA + 6144;
    float* sh = sm + 49152;
    float4* sxf = (float4*)(sm + 49152 + 512);

    const int tid = threadIdx.x;
    const int j = tid & 127;
    const int u = tid >> 7;
    const int b0 = blockIdx.x * 4;

    {
        const float4* g4 = (const float4*)WTI;
        float4* s4 = (float4*)sm;
        #pragma unroll 4
        for (int i = tid; i < 6144; i += 512) s4[i] = g4[i];
        #pragma unroll 4
        for (int i = tid; i < 6144; i += 512) s4[6144 + i] = g4[8192 + i];
    }
    ulonglong2 wtA[4], wtB[4];
    {
        const ulonglong2* gA = (const ulonglong2*)WTI;
        const ulonglong2* gB = gA + 8192;
        int kt = KPSM + u * 4;
        #pragma unroll
        for (int i = 0; i < 4; i++) {
            wtA[i] = gA[(size_t)(kt + i) * 128 + j];
            wtB[i] = gB[(size_t)(kt + i) * 128 + j];
        }
    }
    sh[tid] = 0.0f;

    const int klo = u * 24;
    const int kplo = u * 12;

    const size_t xbase = ((size_t)(b0 + u)) * TT * GG + j;
    float* houtP = hout ? hout + ((size_t)(b0 + u)) * TT * HH + j : (float*)0;

    float xc0 = xg[xbase], xc1 = xg[xbase + 128], xc2 = xg[xbase + 256], xc3 = xg[xbase + 384];

    float cc = 0.0f, hh = 0.0f;
    __syncthreads();

    for (int t = 0; t < TT; t++) {
        ull a00 = 0, a01 = 0, a02 = 0, a03 = 0;
        ull a10 = 0, a11 = 0, a12 = 0, a13 = 0;
        ull a20 = 0, a21 = 0, a22 = 0, a23 = 0;
        ull a30 = 0, a31 = 0, a32 = 0, a33 = 0;

        float xn0 = 0, xn1 = 0, xn2 = 0, xn3 = 0;
        if (t + 1 < TT) {
            size_t o = xbase + (size_t)(t + 1) * GG;
            xn0 = xg[o]; xn1 = xg[o + 128]; xn2 = xg[o + 256]; xn3 = xg[o + 384];
        }

        #pragma unroll
        for (int g = 0; g < 6; g++) {
            int kb = klo + g * 4;
            ulonglong2 H0 = *(const ulonglong2*)(sh + kb);
            ulonglong2 H1 = *(const ulonglong2*)(sh + 128 + kb);
            ulonglong2 H2 = *(const ulonglong2*)(sh + 256 + kb);
            ulonglong2 H3 = *(const ulonglong2*)(sh + 384 + kb);
            int kpi = (kplo + g * 2) * 128 + j;
            ulonglong2 w0 = swA[kpi];
            ulonglong2 w1 = swB[kpi];
            MAC4(H0.x, H1.x, H2.x, H3.x, w0, w1);
            ulonglong2 w2 = swA[kpi + 128];
            ulonglong2 w3 = swB[kpi + 128];
            MAC4(H0.y, H1.y, H2.y, H3.y, w2, w3);
        }
        #pragma unroll
        for (int g = 0; g < 2; g++) {
            int kb = 96 + u * 8 + g * 4;
            ulonglong2 H0 = *(const ulonglong2*)(sh + kb);
            ulonglong2 H1 = *(const ulonglong2*)(sh + 128 + kb);
            ulonglong2 H2 = *(const ulonglong2*)(sh + 256 + kb);
            ulonglong2 H3 = *(const ulonglong2*)(sh + 384 + kb);
            MAC4(H0.x, H1.x, H2.x, H3.x, wtA[g * 2], wtB[g * 2]);
            MAC4(H0.y, H1.y, H2.y, H3.y, wtA[g * 2 + 1], wtB[g * 2 + 1]);
        }

        float4 s0, s1, s2, s3;
        s0.x = red2(a00); s0.y = red2(a01); s0.z = red2(a02); s0.w = red2(a03);
        s1.x = red2(a10); s1.y = red2(a11); s1.z = red2(a12); s1.w = red2(a13);
        s2.x = red2(a20); s2.y = red2(a21); s2.z = red2(a22); s2.w = red2(a23);
        s3.x = red2(a30); s3.y = red2(a31); s3.z = red2(a32); s3.w = red2(a33);

        if (u != 0) sxf[(0 * 3 + (u - 1)) * 128 + j] = s0;
        if (u != 1) sxf[(1 * 3 + ((u == 0) ? 0 : u - 1)) * 128 + j] = s1;
        if (u != 2) sxf[(2 * 3 + ((u == 3) ? 2 : u)) * 128 + j] = s2;
        if (u != 3) sxf[(3 * 3 + u) * 128 + j] = s3;
        __syncthreads();
        {
            float4 own = (u == 0) ? s0 : (u == 1) ? s1 : (u == 2) ? s2 : s3;
            float4 p0 = sxf[u * 384 + j];
            float4 p1 = sxf[u * 384 + 128 + j];
            float4 p2 = sxf[u * 384 + 256 + j];
            float gi = own.x + xc0 + p0.x + p1.x + p2.x;
            float gf = own.y + xc1 + p0.y + p1.y + p2.y;
            float gg2 = own.z + xc2 + p0.z + p1.z + p2.z;
            float go = own.w + xc3 + p0.w + p1.w + p2.w;

            float ii = sigf(gi), ff = sigf(gf), g = tanhx(gg2), oo = sigf(go);
            cc = ff * cc + ii * g;
            hh = oo * tanhx(cc);

            sh[u * 128 + j] = hh;
            if (hout) houtP[(size_t)t * HH] = hh;
        }
        xc0 = xn0; xc1 = xn1; xc2 = xn2; xc3 = xn3;
        __syncthreads();
    }

    if (hlast) hlast[(b0 + u) * HH + j] = hh;
}

// -------- MLP head --------
__device__ __forceinline__ float celuf(float x) { return x > 0.0f ? x : expm1f(x); }

__global__ void __launch_bounds__(256) head_kernel(
    const float* __restrict__ hlast,
    const float* __restrict__ W1, const float* __restrict__ b1,
    const float* __restrict__ W2, const float* __restrict__ b2,
    float* __restrict__ out)
{
    const int b = blockIdx.x;
    const int tid = threadIdx.x;
    __shared__ float sl[HH];
    __shared__ float sy[DLL];

    if (tid < HH) sl[tid] = hlast[b * HH + tid];
    __syncthreads();

    float s = b1[tid];
    const float* w = W1 + (size_t)tid * HH;
    #pragma unroll 8
    for (int k = 0; k < HH; k++) s += sl[k] * w[k];
    sy[tid] = celuf(s);
    __syncthreads();

    if (tid < OUTD) {
        float s2 = b2[tid];
        const float* w2 = W2 + (size_t)tid * DLL;
        #pragma unroll 8
        for (int k = 0; k < DLL; k++) s2 += sy[k] * w2[k];
        out[b * OUTD + tid] = celuf(s2);
    }
}

__global__ void zero_tail(float* __restrict__ p, int n) {
    int i = blockIdx.x * 256 + threadIdx.x;
    if (i < n) p[i] = 0.0f;
}

// -------- launch --------
extern "C" void kernel_launch(void* const* d_in, const int* in_sizes, int n_in,
                              void* d_out, int out_size)
{
    const float* x    = (const float*)d_in[0];
    const float* Wih0 = (const float*)d_in[1];
    const float* Whh0 = (const float*)d_in[2];
    const float* bih0 = (const float*)d_in[3];
    const float* bhh0 = (const float*)d_in[4];
    const float* Wih1 = (const float*)d_in[5];
    const float* Whh1 = (const float*)d_in[6];
    const float* bih1 = (const float*)d_in[7];
    const float* bhh1 = (const float*)d_in[8];
    const float* W1   = (const float*)d_in[9];
    const float* b1   = (const float*)d_in[10];
    const float* W2   = (const float*)d_in[11];
    const float* b2   = (const float*)d_in[12];
    float* out = (float*)d_out;

    float *xgp, *h0p, *hlastp, *wt0p, *wt1p;
    cudaGetSymbolAddress((void**)&xgp,    g_xg);
    cudaGetSymbolAddress((void**)&h0p,    g_h0);
    cudaGetSymbolAddress((void**)&hlastp, g_hlast);
    cudaGetSymbolAddress((void**)&wt0p,   g_WT0);
    cudaGetSymbolAddress((void**)&wt1p,   g_WT1);

    // dynamic smem: A(2x128xstride) + W(2x64xstride) bf16 + 512-float bias
    const int smem_k128 = (2 * 128 * (HH + 8) + 2 * 64 * (HH + 8)) * 2 + 512 * 4;      // 106496
    const int smem_k32  = (2 * 128 * (INDIM + 8) + 2 * 64 * (INDIM + 8)) * 2 + 512 * 4; // 32768

    cudaFuncSetAttribute(lstm_layer_kernel, cudaFuncAttributeMaxDynamicSharedMemorySize, LSTM_SMEM);
    cudaFuncSetAttribute(mma_pregate,       cudaFuncAttributeMaxDynamicSharedMemorySize, smem_k128);

    prep_whh<<<256, 256>>>(Whh0, wt0p);
    prep_whh<<<256, 256>>>(Whh1, wt1p);

    // layer 0: pre-gates (mma.sync bf16 split, K=32) then recurrence
    mma_pregate<<<M_TOT / 128, 256, smem_k32>>>(x, Wih0, bih0, bhh0, xgp, INDIM);
    lstm_layer_kernel<<<BB / 4, 512, LSTM_SMEM>>>(xgp, wt0p, h0p, nullptr);

    // layer 1: pre-gates (mma.sync bf16 split, K=128) then recurrence
    mma_pregate<<<M_TOT / 128, 256, smem_k128>>>(h0p, Wih1, bih1, bhh1, xgp, HH);
    lstm_layer_kernel<<<BB / 4, 512, LSTM_SMEM>>>(xgp, wt1p, nullptr, hlastp);

    head_kernel<<<BB, 256>>>(hlastp, W1, b1, W2, b2, out);
    int tail = out_size - BB * OUTD;
    if (tail > 0)
        zero_tail<<<(tail + 255) / 256, 256>>>(out + BB * OUTD, tail);
}

// round 14
// speedup vs baseline: 1.6795x; 1.0080x over previous
#include <cuda_runtime.h>
#include <cuda_bf16.h>
#include <cstdint>
#include <cstddef>

typedef unsigned long long ull;

#define BB 512
#define TT 1024
#define INDIM 32
#define HH 128
#define GG 512            // 4*H
#define DLL 256
#define OUTD 32
#define M_TOT (BB*TT)     // 524288

// ---- lstm smem layout (round-4/7, proven — FROZEN) ----
#define KPSM 48
#define LSTM_SMEM ((49152 + 512 + 6144) * 4)    // 223232 bytes

// -------- device scratch (static; no runtime allocation) --------
__device__ float g_xg[(size_t)M_TOT * GG];
__device__ float g_h0[(size_t)M_TOT * HH];
__device__ float g_hlast[BB * HH];
__device__ float g_WT0[HH * GG];
__device__ float g_WT1[HH * GG];
// pre-split Wih images: [nb(8)][hi 64*stride | lo 64*stride] bf16, stride = K+8
__device__ __nv_bfloat16 g_Wimg0[8 * 128 * (INDIM + 8)];   // 80 KB
__device__ __nv_bfloat16 g_Wimg1[8 * 128 * (HH + 8)];      // 272 KB

// ---------------- f32x2 helpers (lstm) ----------------
__device__ __forceinline__ ull fma2(ull a, ull b, ull c) {
    ull d;
    asm("fma.rn.f32x2 %0, %1, %2, %3;" : "=l"(d) : "l"(a), "l"(b), "l"(c));
    return d;
}
__device__ __forceinline__ void unpack2(ull v, float& x, float& y) {
    unsigned a, b;
    asm("mov.b64 {%0, %1}, %2;" : "=r"(a), "=r"(b) : "l"(v));
    x = __uint_as_float(a);
    y = __uint_as_float(b);
}
__device__ __forceinline__ float red2(ull v) {
    float a, b;
    unpack2(v, a, b);
    return a + b;
}
__device__ __forceinline__ float sigf(float x)  { return __fdividef(1.0f, 1.0f + __expf(-x)); }
__device__ __forceinline__ float tanhx(float x) { return __fdividef(2.0f, 1.0f + __expf(-2.0f * x)) - 1.0f; }

// -------- interleave Whh for lstm (unchanged) --------
__global__ void prep_whh(const float* __restrict__ W, float* __restrict__ WTI) {
    int idx = blockIdx.x * 256 + threadIdx.x;
    if (idx < HH * GG) {
        int r = idx >> 15;
        int rem = idx & 32767;
        int kp = rem >> 9;
        int rem2 = rem & 511;
        int j = rem2 >> 2;
        int t = rem2 & 3;
        int qq = t >> 1;
        int e = t & 1;
        int q = r * 2 + qq;
        WTI[idx] = W[(q * HH + j) * HH + 2 * kp + e];
    }
}

// -------- pre-split Wih [512][K] into smem-image bf16 hi/lo blocks --------
__global__ void prep_wsplit(const float* __restrict__ W, __nv_bfloat16* __restrict__ img, int K) {
    int idx = blockIdx.x * 256 + threadIdx.x;
    if (idx < 512 * K) {
        int row = idx / K;
        int col = idx - row * K;
        int nb = row >> 6;
        int r = row & 63;
        int stride = K + 8;
        float v = W[idx];
        __nv_bfloat16 hi = __float2bfloat16(v);
        __nv_bfloat16 lo = __float2bfloat16(v - __bfloat162float(hi));
        size_t base = (size_t)nb * (128 * stride) + r * stride + col;
        img[base] = hi;
        img[base + 64 * stride] = lo;
    }
}

// ================= mma.sync bf16 hi/lo pre-gate GEMM =================
// C[m][n] = sum_k A[m][k]*W[n][k] + ba[n] + bb[n]
// grid (M/128): A tile converted once per CTA; 8 N-blocks of 64 rows of W
// copied from the pre-split global image (no conversion); 2 CTAs/SM.
// 8 warps: warp tile 32m x 32n. 3-MMA split: Ahi*Whi + Alo*Whi + Ahi*Wlo.

#define MMA_BF16(D, A0, A1, A2, A3, B0, B1) \
    asm volatile( \
        "mma.sync.aligned.m16n8k16.row.col.f32.bf16.bf16.f32 " \
        "{%0,%1,%2,%3}, {%4,%5,%6,%7}, {%8,%9}, {%0,%1,%2,%3};" \
        : "+f"((D)[0]), "+f"((D)[1]), "+f"((D)[2]), "+f"((D)[3]) \
        : "r"(A0), "r"(A1), "r"(A2), "r"(A3), "r"(B0), "r"(B1))

__device__ __forceinline__ void cvt_hilo(float4 v, uint2& oh, uint2& ol) {
    __nv_bfloat162 h01 = __floats2bfloat162_rn(v.x, v.y);
    __nv_bfloat162 h23 = __floats2bfloat162_rn(v.z, v.w);
    __nv_bfloat162 l01 = __floats2bfloat162_rn(v.x - __bfloat162float(h01.x),
                                               v.y - __bfloat162float(h01.y));
    __nv_bfloat162 l23 = __floats2bfloat162_rn(v.z - __bfloat162float(h23.x),
                                               v.w - __bfloat162float(h23.y));
    oh.x = *(uint32_t*)&h01; oh.y = *(uint32_t*)&h23;
    ol.x = *(uint32_t*)&l01; ol.y = *(uint32_t*)&l23;
}

__global__ void __launch_bounds__(256, 2) mma_pregate(
    const float* __restrict__ A,              // [M][K] fp32
    const __nv_bfloat16* __restrict__ Wimg,   // pre-split hi/lo image
    const float* __restrict__ ba, const float* __restrict__ bb,
    float* __restrict__ C,                    // [M][512]
    int K)
{
    extern __shared__ __nv_bfloat16 smem[];
    const int stride = K + 8;
    __nv_bfloat16* sAhi = smem;
    __nv_bfloat16* sAlo = sAhi + 128 * stride;
    __nv_bfloat16* sWhi = sAlo + 128 * stride;
    __nv_bfloat16* sWlo = sWhi + 64 * stride;
    float* sbias = (float*)(sWlo + 64 * stride);

    const int tid = threadIdx.x;
    const int lane = tid & 31;
    const int wid = tid >> 5;
    const int wm = wid & 3;              // warp m index: rows wm*32 .. +32
    const int wn = wid >> 2;             // warp n index: cols wn*32 .. +32
    const int g = lane >> 2;
    const int tig = lane & 3;

    const int m0 = blockIdx.x * 128;
    const int kv = K >> 2;

    for (int i = tid; i < 512; i += 256) sbias[i] = ba[i] + bb[i];

    // convert A tile once: 128 rows x K
    for (int idx = tid; idx < 128 * kv; idx += 256) {
        int row = idx / kv;
        int q = idx - row * kv;
        float4 v = *(const float4*)(A + (size_t)(m0 + row) * K + q * 4);
        uint2 oh, ol;
        cvt_hilo(v, oh, ol);
        *(uint2*)(&sAhi[row * stride + q * 4]) = oh;
        *(uint2*)(&sAlo[row * stride + q * 4]) = ol;
    }

    const int wcpy = (128 * stride) / 8;     // float4s per W block (hi+lo)

    for (int nb = 0; nb < 8; nb++) {
        __syncthreads();   // prior mma done reading W (and A ready at nb=0)
        // copy pre-split W block (hi then lo, contiguous image)
        {
            const float4* src = (const float4*)(Wimg + (size_t)nb * (128 * stride));
            float4* dst = (float4*)sWhi;
            for (int i = tid; i < wcpy; i += 256) dst[i] = src[i];
        }
        __syncthreads();

        float d[2][4][4];
        #pragma unroll
        for (int mf = 0; mf < 2; mf++)
            #pragma unroll
            for (int nf = 0; nf < 4; nf++)
                #pragma unroll
                for (int e = 0; e < 4; e++) d[mf][nf][e] = 0.0f;

        const int nks = K >> 4;
        for (int ks = 0; ks < nks; ks++) {
            const int c0 = ks * 16 + 2 * tig;
            const int c1 = c0 + 8;

            uint32_t AH[2][4], AL[2][4];
            #pragma unroll
            for (int mf = 0; mf < 2; mf++) {
                int r0 = (wm * 32 + mf * 16 + g) * stride;
                int r8 = r0 + 8 * stride;
                AH[mf][0] = *(const uint32_t*)(&sAhi[r0 + c0]);
                AH[mf][1] = *(const uint32_t*)(&sAhi[r8 + c0]);
                AH[mf][2] = *(const uint32_t*)(&sAhi[r0 + c1]);
                AH[mf][3] = *(const uint32_t*)(&sAhi[r8 + c1]);
                AL[mf][0] = *(const uint32_t*)(&sAlo[r0 + c0]);
                AL[mf][1] = *(const uint32_t*)(&sAlo[r8 + c0]);
                AL[mf][2] = *(const uint32_t*)(&sAlo[r0 + c1]);
                AL[mf][3] = *(const uint32_t*)(&sAlo[r8 + c1]);
            }
            #pragma unroll
            for (int nf = 0; nf < 4; nf++) {
                int rb = (wn * 32 + nf * 8 + g) * stride;
                uint32_t BH0 = *(const uint32_t*)(&sWhi[rb + c0]);
                uint32_t BH1 = *(const uint32_t*)(&sWhi[rb + c1]);
                uint32_t BL0 = *(const uint32_t*)(&sWlo[rb + c0]);
                uint32_t BL1 = *(const uint32_t*)(&sWlo[rb + c1]);
                #pragma unroll
                for (int mf = 0; mf < 2; mf++) {
                    MMA_BF16(d[mf][nf], AH[mf][0], AH[mf][1], AH[mf][2], AH[mf][3], BH0, BH1);
                    MMA_BF16(d[mf][nf], AL[mf][0], AL[mf][1], AL[mf][2], AL[mf][3], BH0, BH1);
                    MMA_BF16(d[mf][nf], AH[mf][0], AH[mf][1], AH[mf][2], AH[mf][3], BL0, BL1);
                }
            }
        }

        // epilogue: add bias, store float2 pairs
        #pragma unroll
        for (int mf = 0; mf < 2; mf++) {
            int r0 = wm * 32 + mf * 16 + g;
            #pragma unroll
            for (int nf = 0; nf < 4; nf++) {
                int nl = nb * 64 + wn * 32 + nf * 8 + 2 * tig;
                float bx = sbias[nl];
                float by = sbias[nl + 1];
                float2 o0, o1;
                o0.x = d[mf][nf][0] + bx; o0.y = d[mf][nf][1] + by;
                o1.x = d[mf][nf][2] + bx; o1.y = d[mf][nf][3] + by;
                *(float2*)(C + (size_t)(m0 + r0) * GG + nl) = o0;
                *(float2*)(C + (size_t)(m0 + r0 + 8) * GG + nl) = o1;
            }
        }
    }
}

// -------- LSTM recurrence (round-4/7, proven — FROZEN) --------
#define MAC4(HV0, HV1, HV2, HV3, W0, W1) { \
    a00 = fma2(HV0, W0.x, a00); a01 = fma2(HV0, W0.y, a01); \
    a02 = fma2(HV0, W1.x, a02); a03 = fma2(HV0, W1.y, a03); \
    a10 = fma2(HV1, W0.x, a10); a11 = fma2(HV1, W0.y, a11); \
    a12 = fma2(HV1, W1.x, a12); a13 = fma2(HV1, W1.y, a13); \
    a20 = fma2(HV2, W0.x, a20); a21 = fma2(HV2, W0.y, a21); \
    a22 = fma2(HV2, W1.x, a22); a23 = fma2(HV2, W1.y, a23); \
    a30 = fma2(HV3, W0.x, a30); a31 = fma2(HV3, W0.y, a31); \
    a32 = fma2(HV3, W1.x, a32); a33 = fma2(HV3, W1.y, a33); }

__global__ void __launch_bounds__(512, 1) lstm_layer_kernel(
    const float* __restrict__ xg,
    const float* __restrict__ WTI,
    float* __restrict__ hout,
    float* __restrict__ hlast)
{
    extern __shared__ float sm[];
    const ulonglong2* swA = (const ulonglong2*)sm;
    const ulonglong2* swB = swA + 6144;
    float* sh = sm + 49152;
    float4* sxf = (float4*)(sm + 49152 + 512);

    const int tid = threadIdx.x;
    const int j = tid & 127;
    const int u = tid >> 7;
    const int b0 = blockIdx.x * 4;

    {
        const float4* g4 = (const float4*)WTI;
        float4* s4 = (float4*)sm;
        #pragma unroll 4
        for (int i = tid; i < 6144; i += 512) s4[i] = g4[i];
        #pragma unroll 4
        for (int i = tid; i < 6144; i += 512) s4[6144 + i] = g4[8192 + i];
    }
    ulonglong2 wtA[4], wtB[4];
    {
        const ulonglong2* gA = (const ulonglong2*)WTI;
        const ulonglong2* gB = gA + 8192;
        int kt = KPSM + u * 4;
        #pragma unroll
        for (int i = 0; i < 4; i++) {
            wtA[i] = gA[(size_t)(kt + i) * 128 + j];
            wtB[i] = gB[(size_t)(kt + i) * 128 + j];
        }
    }
    sh[tid] = 0.0f;

    const int klo = u * 24;
    const int kplo = u * 12;

    const size_t xbase = ((size_t)(b0 + u)) * TT * GG + j;
    float* houtP = hout ? hout + ((size_t)(b0 + u)) * TT * HH + j : (float*)0;

    float xc0 = xg[xbase], xc1 = xg[xbase + 128], xc2 = xg[xbase + 256], xc3 = xg[xbase + 384];

    float cc = 0.0f, hh = 0.0f;
    __syncthreads();

    for (int t = 0; t < TT; t++) {
        ull a00 = 0, a01 = 0, a02 = 0, a03 = 0;
        ull a10 = 0, a11 = 0, a12 = 0, a13 = 0;
        ull a20 = 0, a21 = 0, a22 = 0, a23 = 0;
        ull a30 = 0, a31 = 0, a32 = 0, a33 = 0;

        float xn0 = 0, xn1 = 0, xn2 = 0, xn3 = 0;
        if (t + 1 < TT) {
            size_t o = xbase + (size_t)(t + 1) * GG;
            xn0 = xg[o]; xn1 = xg[o + 128]; xn2 = xg[o + 256]; xn3 = xg[o + 384];
        }

        #pragma unroll
        for (int g = 0; g < 6; g++) {
            int kb = klo + g * 4;
            ulonglong2 H0 = *(const ulonglong2*)(sh + kb);
            ulonglong2 H1 = *(const ulonglong2*)(sh + 128 + kb);
            ulonglong2 H2 = *(const ulonglong2*)(sh + 256 + kb);
            ulonglong2 H3 = *(const ulonglong2*)(sh + 384 + kb);
            int kpi = (kplo + g * 2) * 128 + j;
            ulonglong2 w0 = swA[kpi];
            ulonglong2 w1 = swB[kpi];
            MAC4(H0.x, H1.x, H2.x, H3.x, w0, w1);
            ulonglong2 w2 = swA[kpi + 128];
            ulonglong2 w3 = swB[kpi + 128];
            MAC4(H0.y, H1.y, H2.y, H3.y, w2, w3);
        }
        #pragma unroll
        for (int g = 0; g < 2; g++) {
            int kb = 96 + u * 8 + g * 4;
            ulonglong2 H0 = *(const ulonglong2*)(sh + kb);
            ulonglong2 H1 = *(const ulonglong2*)(sh + 128 + kb);
            ulonglong2 H2 = *(const ulonglong2*)(sh + 256 + kb);
            ulonglong2 H3 = *(const ulonglong2*)(sh + 384 + kb);
            MAC4(H0.x, H1.x, H2.x, H3.x, wtA[g * 2], wtB[g * 2]);
            MAC4(H0.y, H1.y, H2.y, H3.y, wtA[g * 2 + 1], wtB[g * 2 + 1]);
        }

        float4 s0, s1, s2, s3;
        s0.x = red2(a00); s0.y = red2(a01); s0.z = red2(a02); s0.w = red2(a03);
        s1.x = red2(a10); s1.y = red2(a11); s1.z = red2(a12); s1.w = red2(a13);
        s2.x = red2(a20); s2.y = red2(a21); s2.z = red2(a22); s2.w = red2(a23);
        s3.x = red2(a30); s3.y = red2(a31); s3.z = red2(a32); s3.w = red2(a33);

        if (u != 0) sxf[(0 * 3 + (u - 1)) * 128 + j] = s0;
        if (u != 1) sxf[(1 * 3 + ((u == 0) ? 0 : u - 1)) * 128 + j] = s1;
        if (u != 2) sxf[(2 * 3 + ((u == 3) ? 2 : u)) * 128 + j] = s2;
        if (u != 3) sxf[(3 * 3 + u) * 128 + j] = s3;
        __syncthreads();
        {
            float4 own = (u == 0) ? s0 : (u == 1) ? s1 : (u == 2) ? s2 : s3;
            float4 p0 = sxf[u * 384 + j];
            float4 p1 = sxf[u * 384 + 128 + j];
            float4 p2 = sxf[u * 384 + 256 + j];
            float gi = own.x + xc0 + p0.x + p1.x + p2.x;
            float gf = own.y + xc1 + p0.y + p1.y + p2.y;
            float gg2 = own.z + xc2 + p0.z + p1.z + p2.z;
            float go = own.w + xc3 + p0.w + p1.w + p2.w;

            float ii = sigf(gi), ff = sigf(gf), g = tanhx(gg2), oo = sigf(go);
            cc = ff * cc + ii * g;
            hh = oo * tanhx(cc);

            sh[u * 128 + j] = hh;
            if (hout) houtP[(size_t)t * HH] = hh;
        }
        xc0 = xn0; xc1 = xn1; xc2 = xn2; xc3 = xn3;
        __syncthreads();
    }

    if (hlast) hlast[(b0 + u) * HH + j] = hh;
}

// -------- MLP head --------
__device__ __forceinline__ float celuf(float x) { return x > 0.0f ? x : expm1f(x); }

__global__ void __launch_bounds__(256) head_kernel(
    const float* __restrict__ hlast,
    const float* __restrict__ W1, const float* __restrict__ b1,
    const float* __restrict__ W2, const float* __restrict__ b2,
    float* __restrict__ out)
{
    const int b = blockIdx.x;
    const int tid = threadIdx.x;
    __shared__ float sl[HH];
    __shared__ float sy[DLL];

    if (tid < HH) sl[tid] = hlast[b * HH + tid];
    __syncthreads();

    float s = b1[tid];
    const float* w = W1 + (size_t)tid * HH;
    #pragma unroll 8
    for (int k = 0; k < HH; k++) s += sl[k] * w[k];
    sy[tid] = celuf(s);
    __syncthreads();

    if (tid < OUTD) {
        float s2 = b2[tid];
        const float* w2 = W2 + (size_t)tid * DLL;
        #pragma unroll 8
        for (int k = 0; k < DLL; k++) s2 += sy[k] * w2[k];
        out[b * OUTD + tid] = celuf(s2);
    }
}

__global__ void zero_tail(float* __restrict__ p, int n) {
    int i = blockIdx.x * 256 + threadIdx.x;
    if (i < n) p[i] = 0.0f;
}

// -------- launch --------
extern "C" void kernel_launch(void* const* d_in, const int* in_sizes, int n_in,
                              void* d_out, int out_size)
{
    const float* x    = (const float*)d_in[0];
    const float* Wih0 = (const float*)d_in[1];
    const float* Whh0 = (const float*)d_in[2];
    const float* bih0 = (const float*)d_in[3];
    const float* bhh0 = (const float*)d_in[4];
    const float* Wih1 = (const float*)d_in[5];
    const float* Whh1 = (const float*)d_in[6];
    const float* bih1 = (const float*)d_in[7];
    const float* bhh1 = (const float*)d_in[8];
    const float* W1   = (const float*)d_in[9];
    const float* b1   = (const float*)d_in[10];
    const float* W2   = (const float*)d_in[11];
    const float* b2   = (const float*)d_in[12];
    float* out = (float*)d_out;

    float *xgp, *h0p, *hlastp, *wt0p, *wt1p;
    __nv_bfloat16 *wimg0, *wimg1;
    cudaGetSymbolAddress((void**)&xgp,    g_xg);
    cudaGetSymbolAddress((void**)&h0p,    g_h0);
    cudaGetSymbolAddress((void**)&hlastp, g_hlast);
    cudaGetSymbolAddress((void**)&wt0p,   g_WT0);
    cudaGetSymbolAddress((void**)&wt1p,   g_WT1);
    cudaGetSymbolAddress((void**)&wimg0,  g_Wimg0);
    cudaGetSymbolAddress((void**)&wimg1,  g_Wimg1);

    // dynamic smem: A(2x128xstride) + W(2x64xstride) bf16 + 512-float bias
    const int smem_k128 = (2 * 128 * (HH + 8) + 2 * 64 * (HH + 8)) * 2 + 512 * 4;      // 106496
    const int smem_k32  = (2 * 128 * (INDIM + 8) + 2 * 64 * (INDIM + 8)) * 2 + 512 * 4; // 32768

    cudaFuncSetAttribute(lstm_layer_kernel, cudaFuncAttributeMaxDynamicSharedMemorySize, LSTM_SMEM);
    cudaFuncSetAttribute(mma_pregate,       cudaFuncAttributeMaxDynamicSharedMemorySize, smem_k128);

    prep_whh<<<256, 256>>>(Whh0, wt0p);
    prep_whh<<<256, 256>>>(Whh1, wt1p);
    prep_wsplit<<<(512 * INDIM + 255) / 256, 256>>>(Wih0, wimg0, INDIM);
    prep_wsplit<<<(512 * HH + 255) / 256, 256>>>(Wih1, wimg1, HH);

    // layer 0: pre-gates (mma.sync bf16 split, K=32) then recurrence
    mma_pregate<<<M_TOT / 128, 256, smem_k32>>>(x, wimg0, bih0, bhh0, xgp, INDIM);
    lstm_layer_kernel<<<BB / 4, 512, LSTM_SMEM>>>(xgp, wt0p, h0p, nullptr);

    // layer 1: pre-gates (mma.sync bf16 split, K=128) then recurrence
    mma_pregate<<<M_TOT / 128, 256, smem_k128>>>(h0p, wimg1, bih1, bhh1, xgp, HH);
    lstm_layer_kernel<<<BB / 4, 512, LSTM_SMEM>>>(xgp, wt1p, nullptr, hlastp);

    head_kernel<<<BB, 256>>>(hlastp, W1, b1, W2, b2, out);
    int tail = out_size - BB * OUTD;
    if (tail > 0)
        zero_tail<<<(tail + 255) / 256, 256>>>(out + BB * OUTD, tail);
}

// round 15
// speedup vs baseline: 1.7081x; 1.0171x over previous
#include <cuda_runtime.h>
#include <cuda_bf16.h>
#include <cstdint>
#include <cstddef>

typedef unsigned long long ull;

#define BB 512
#define TT 1024
#define INDIM 32
#define HH 128
#define GG 512            // 4*H
#define DLL 256
#define OUTD 32
#define M_TOT (BB*TT)     // 524288

// ---- lstm smem layout (round-4/7, proven — FROZEN) ----
#define KPSM 48
#define LSTM_SMEM ((49152 + 512 + 6144) * 4)    // 223232 bytes

// -------- device scratch (static; no runtime allocation) --------
__device__ float g_xg[(size_t)M_TOT * GG];
__device__ float g_h0[(size_t)M_TOT * HH];
__device__ float g_hlast[BB * HH];
__device__ float g_WT0[HH * GG];
__device__ float g_WT1[HH * GG];
// pre-split Wih images: [nb(8)][hi 64*stride | lo 64*stride] bf16, stride = K+8
__device__ __nv_bfloat16 g_Wimg0[8 * 128 * (INDIM + 8)];   // 80 KB
__device__ __nv_bfloat16 g_Wimg1[8 * 128 * (HH + 8)];      // 272 KB

// ---------------- f32x2 helpers (lstm) ----------------
__device__ __forceinline__ ull fma2(ull a, ull b, ull c) {
    ull d;
    asm("fma.rn.f32x2 %0, %1, %2, %3;" : "=l"(d) : "l"(a), "l"(b), "l"(c));
    return d;
}
__device__ __forceinline__ void unpack2(ull v, float& x, float& y) {
    unsigned a, b;
    asm("mov.b64 {%0, %1}, %2;" : "=r"(a), "=r"(b) : "l"(v));
    x = __uint_as_float(a);
    y = __uint_as_float(b);
}
__device__ __forceinline__ float red2(ull v) {
    float a, b;
    unpack2(v, a, b);
    return a + b;
}
__device__ __forceinline__ float sigf(float x)  { return __fdividef(1.0f, 1.0f + __expf(-x)); }
__device__ __forceinline__ float tanhx(float x) { return __fdividef(2.0f, 1.0f + __expf(-2.0f * x)) - 1.0f; }

// -------- interleave Whh for lstm (unchanged) --------
__global__ void prep_whh(const float* __restrict__ W, float* __restrict__ WTI) {
    int idx = blockIdx.x * 256 + threadIdx.x;
    if (idx < HH * GG) {
        int r = idx >> 15;
        int rem = idx & 32767;
        int kp = rem >> 9;
        int rem2 = rem & 511;
        int j = rem2 >> 2;
        int t = rem2 & 3;
        int qq = t >> 1;
        int e = t & 1;
        int q = r * 2 + qq;
        WTI[idx] = W[(q * HH + j) * HH + 2 * kp + e];
    }
}

// -------- pre-split Wih [512][K] into smem-image bf16 hi/lo blocks --------
__global__ void prep_wsplit(const float* __restrict__ W, __nv_bfloat16* __restrict__ img, int K) {
    int idx = blockIdx.x * 256 + threadIdx.x;
    if (idx < 512 * K) {
        int row = idx / K;
        int col = idx - row * K;
        int nb = row >> 6;
        int r = row & 63;
        int stride = K + 8;
        float v = W[idx];
        __nv_bfloat16 hi = __float2bfloat16(v);
        __nv_bfloat16 lo = __float2bfloat16(v - __bfloat162float(hi));
        size_t base = (size_t)nb * (128 * stride) + r * stride + col;
        img[base] = hi;
        img[base + 64 * stride] = lo;
    }
}

#define MMA_BF16(D, A0, A1, A2, A3, B0, B1) \
    asm volatile( \
        "mma.sync.aligned.m16n8k16.row.col.f32.bf16.bf16.f32 " \
        "{%0,%1,%2,%3}, {%4,%5,%6,%7}, {%8,%9}, {%0,%1,%2,%3};" \
        : "+f"((D)[0]), "+f"((D)[1]), "+f"((D)[2]), "+f"((D)[3]) \
        : "r"(A0), "r"(A1), "r"(A2), "r"(A3), "r"(B0), "r"(B1))

__device__ __forceinline__ void cvt_hilo(float4 v, uint2& oh, uint2& ol) {
    __nv_bfloat162 h01 = __floats2bfloat162_rn(v.x, v.y);
    __nv_bfloat162 h23 = __floats2bfloat162_rn(v.z, v.w);
    __nv_bfloat162 l01 = __floats2bfloat162_rn(v.x - __bfloat162float(h01.x),
                                               v.y - __bfloat162float(h01.y));
    __nv_bfloat162 l23 = __floats2bfloat162_rn(v.z - __bfloat162float(h23.x),
                                               v.w - __bfloat162float(h23.y));
    oh.x = *(uint32_t*)&h01; oh.y = *(uint32_t*)&h23;
    ol.x = *(uint32_t*)&l01; ol.y = *(uint32_t*)&l23;
}

// ================= K=128 pre-gate GEMM (round-14, proven) =================
__global__ void __launch_bounds__(256, 2) mma_pregate(
    const float* __restrict__ A,              // [M][K] fp32
    const __nv_bfloat16* __restrict__ Wimg,   // pre-split hi/lo image
    const float* __restrict__ ba, const float* __restrict__ bb,
    float* __restrict__ C,                    // [M][512]
    int K)
{
    extern __shared__ __nv_bfloat16 smem[];
    const int stride = K + 8;
    __nv_bfloat16* sAhi = smem;
    __nv_bfloat16* sAlo = sAhi + 128 * stride;
    __nv_bfloat16* sWhi = sAlo + 128 * stride;
    __nv_bfloat16* sWlo = sWhi + 64 * stride;
    float* sbias = (float*)(sWlo + 64 * stride);

    const int tid = threadIdx.x;
    const int lane = tid & 31;
    const int wid = tid >> 5;
    const int wm = wid & 3;
    const int wn = wid >> 2;
    const int g = lane >> 2;
    const int tig = lane & 3;

    const int m0 = blockIdx.x * 128;
    const int kv = K >> 2;

    for (int i = tid; i < 512; i += 256) sbias[i] = ba[i] + bb[i];

    for (int idx = tid; idx < 128 * kv; idx += 256) {
        int row = idx / kv;
        int q = idx - row * kv;
        float4 v = *(const float4*)(A + (size_t)(m0 + row) * K + q * 4);
        uint2 oh, ol;
        cvt_hilo(v, oh, ol);
        *(uint2*)(&sAhi[row * stride + q * 4]) = oh;
        *(uint2*)(&sAlo[row * stride + q * 4]) = ol;
    }

    const int wcpy = (128 * stride) / 8;

    for (int nb = 0; nb < 8; nb++) {
        __syncthreads();
        {
            const float4* src = (const float4*)(Wimg + (size_t)nb * (128 * stride));
            float4* dst = (float4*)sWhi;
            for (int i = tid; i < wcpy; i += 256) dst[i] = src[i];
        }
        __syncthreads();

        float d[2][4][4];
        #pragma unroll
        for (int mf = 0; mf < 2; mf++)
            #pragma unroll
            for (int nf = 0; nf < 4; nf++)
                #pragma unroll
                for (int e = 0; e < 4; e++) d[mf][nf][e] = 0.0f;

        const int nks = K >> 4;
        for (int ks = 0; ks < nks; ks++) {
            const int c0 = ks * 16 + 2 * tig;
            const int c1 = c0 + 8;

            uint32_t AH[2][4], AL[2][4];
            #pragma unroll
            for (int mf = 0; mf < 2; mf++) {
                int r0 = (wm * 32 + mf * 16 + g) * stride;
                int r8 = r0 + 8 * stride;
                AH[mf][0] = *(const uint32_t*)(&sAhi[r0 + c0]);
                AH[mf][1] = *(const uint32_t*)(&sAhi[r8 + c0]);
                AH[mf][2] = *(const uint32_t*)(&sAhi[r0 + c1]);
                AH[mf][3] = *(const uint32_t*)(&sAhi[r8 + c1]);
                AL[mf][0] = *(const uint32_t*)(&sAlo[r0 + c0]);
                AL[mf][1] = *(const uint32_t*)(&sAlo[r8 + c0]);
                AL[mf][2] = *(const uint32_t*)(&sAlo[r0 + c1]);
                AL[mf][3] = *(const uint32_t*)(&sAlo[r8 + c1]);
            }
            #pragma unroll
            for (int nf = 0; nf < 4; nf++) {
                int rb = (wn * 32 + nf * 8 + g) * stride;
                uint32_t BH0 = *(const uint32_t*)(&sWhi[rb + c0]);
                uint32_t BH1 = *(const uint32_t*)(&sWhi[rb + c1]);
                uint32_t BL0 = *(const uint32_t*)(&sWlo[rb + c0]);
                uint32_t BL1 = *(const uint32_t*)(&sWlo[rb + c1]);
                #pragma unroll
                for (int mf = 0; mf < 2; mf++) {
                    MMA_BF16(d[mf][nf], AH[mf][0], AH[mf][1], AH[mf][2], AH[mf][3], BH0, BH1);
                    MMA_BF16(d[mf][nf], AL[mf][0], AL[mf][1], AL[mf][2], AL[mf][3], BH0, BH1);
                    MMA_BF16(d[mf][nf], AH[mf][0], AH[mf][1], AH[mf][2], AH[mf][3], BL0, BL1);
                }
            }
        }

        #pragma unroll
        for (int mf = 0; mf < 2; mf++) {
            int r0 = wm * 32 + mf * 16 + g;
            #pragma unroll
            for (int nf = 0; nf < 4; nf++) {
                int nl = nb * 64 + wn * 32 + nf * 8 + 2 * tig;
                float bx = sbias[nl];
                float by = sbias[nl + 1];
                float2 o0, o1;
                o0.x = d[mf][nf][0] + bx; o0.y = d[mf][nf][1] + by;
                o1.x = d[mf][nf][2] + bx; o1.y = d[mf][nf][3] + by;
                *(float2*)(C + (size_t)(m0 + r0) * GG + nl) = o0;
                *(float2*)(C + (size_t)(m0 + r0 + 8) * GG + nl) = o1;
            }
        }
    }
}

// ================= K=32 pre-gate GEMM: ALL W resident, one barrier total =================
// smem: A hi/lo 2x128x40 bf16 (20.5KB) + full W image 8x128x40 bf16 (80KB) + bias (2KB)
// = 102 KB -> 2 CTAs/SM. After the single sync, 8 nb blocks run with no barriers.
__global__ void __launch_bounds__(256, 2) mma_pregate32(
    const float* __restrict__ A,              // [M][32] fp32
    const __nv_bfloat16* __restrict__ Wimg,   // pre-split hi/lo image (stride 40)
    const float* __restrict__ ba, const float* __restrict__ bb,
    float* __restrict__ C)                    // [M][512]
{
    constexpr int K = 32;
    constexpr int stride = 40;
    constexpr int kv = 8;

    extern __shared__ __nv_bfloat16 smem[];
    __nv_bfloat16* sAhi = smem;                       // 128*40
    __nv_bfloat16* sAlo = sAhi + 128 * stride;        // 128*40
    __nv_bfloat16* sW   = sAlo + 128 * stride;        // 8*128*40
    float* sbias = (float*)(sW + 8 * 128 * stride);

    const int tid = threadIdx.x;
    const int lane = tid & 31;
    const int wid = tid >> 5;
    const int wm = wid & 3;
    const int wn = wid >> 2;
    const int g = lane >> 2;
    const int tig = lane & 3;

    const int m0 = blockIdx.x * 128;

    for (int i = tid; i < 512; i += 256) sbias[i] = ba[i] + bb[i];

    // copy full W image once: 8*128*40 bf16 = 5120 float4
    {
        const float4* src = (const float4*)Wimg;
        float4* dst = (float4*)sW;
        #pragma unroll
        for (int i = tid; i < 5120; i += 256) dst[i] = src[i];
    }
    // convert A tile once: 128 rows x 32
    #pragma unroll
    for (int it = 0; it < 4; it++) {
        int idx = tid + it * 256;
        int row = idx >> 3;
        int q = idx & 7;
        float4 v = *(const float4*)(A + (size_t)(m0 + row) * K + q * 4);
        uint2 oh, ol;
        cvt_hilo(v, oh, ol);
        *(uint2*)(&sAhi[row * stride + q * 4]) = oh;
        *(uint2*)(&sAlo[row * stride + q * 4]) = ol;
    }
    __syncthreads();   // the only barrier

    // preload A fragments once (shared across all nb)
    uint32_t AH[2][2][4], AL[2][2][4];   // [ks][mf][frag]
    #pragma unroll
    for (int ks = 0; ks < 2; ks++) {
        const int c0 = ks * 16 + 2 * tig;
        const int c1 = c0 + 8;
        #pragma unroll
        for (int mf = 0; mf < 2; mf++) {
            int r0 = (wm * 32 + mf * 16 + g) * stride;
            int r8 = r0 + 8 * stride;
            AH[ks][mf][0] = *(const uint32_t*)(&sAhi[r0 + c0]);
            AH[ks][mf][1] = *(const uint32_t*)(&sAhi[r8 + c0]);
            AH[ks][mf][2] = *(const uint32_t*)(&sAhi[r0 + c1]);
            AH[ks][mf][3] = *(const uint32_t*)(&sAhi[r8 + c1]);
            AL[ks][mf][0] = *(const uint32_t*)(&sAlo[r0 + c0]);
            AL[ks][mf][1] = *(const uint32_t*)(&sAlo[r8 + c0]);
            AL[ks][mf][2] = *(const uint32_t*)(&sAlo[r0 + c1]);
            AL[ks][mf][3] = *(const uint32_t*)(&sAlo[r8 + c1]);
        }
    }

    for (int nb = 0; nb < 8; nb++) {
        const __nv_bfloat16* sWhi = sW + nb * (128 * stride);
        const __nv_bfloat16* sWlo = sWhi + 64 * stride;

        float d[2][4][4];
        #pragma unroll
        for (int mf = 0; mf < 2; mf++)
            #pragma unroll
            for (int nf = 0; nf < 4; nf++)
                #pragma unroll
                for (int e = 0; e < 4; e++) d[mf][nf][e] = 0.0f;

        #pragma unroll
        for (int ks = 0; ks < 2; ks++) {
            const int c0 = ks * 16 + 2 * tig;
            const int c1 = c0 + 8;
            #pragma unroll
            for (int nf = 0; nf < 4; nf++) {
                int rb = (wn * 32 + nf * 8 + g) * stride;
                uint32_t BH0 = *(const uint32_t*)(&sWhi[rb + c0]);
                uint32_t BH1 = *(const uint32_t*)(&sWhi[rb + c1]);
                uint32_t BL0 = *(const uint32_t*)(&sWlo[rb + c0]);
                uint32_t BL1 = *(const uint32_t*)(&sWlo[rb + c1]);
                #pragma unroll
                for (int mf = 0; mf < 2; mf++) {
                    MMA_BF16(d[mf][nf], AH[ks][mf][0], AH[ks][mf][1], AH[ks][mf][2], AH[ks][mf][3], BH0, BH1);
                    MMA_BF16(d[mf][nf], AL[ks][mf][0], AL[ks][mf][1], AL[ks][mf][2], AL[ks][mf][3], BH0, BH1);
                    MMA_BF16(d[mf][nf], AH[ks][mf][0], AH[ks][mf][1], AH[ks][mf][2], AH[ks][mf][3], BL0, BL1);
                }
            }
        }

        #pragma unroll
        for (int mf = 0; mf < 2; mf++) {
            int r0 = wm * 32 + mf * 16 + g;
            #pragma unroll
            for (int nf = 0; nf < 4; nf++) {
                int nl = nb * 64 + wn * 32 + nf * 8 + 2 * tig;
                float bx = sbias[nl];
                float by = sbias[nl + 1];
                float2 o0, o1;
                o0.x = d[mf][nf][0] + bx; o0.y = d[mf][nf][1] + by;
                o1.x = d[mf][nf][2] + bx; o1.y = d[mf][nf][3] + by;
                *(float2*)(C + (size_t)(m0 + r0) * GG + nl) = o0;
                *(float2*)(C + (size_t)(m0 + r0 + 8) * GG + nl) = o1;
            }
        }
    }
}

// -------- LSTM recurrence (round-4/7, proven — FROZEN) --------
#define MAC4(HV0, HV1, HV2, HV3, W0, W1) { \
    a00 = fma2(HV0, W0.x, a00); a01 = fma2(HV0, W0.y, a01); \
    a02 = fma2(HV0, W1.x, a02); a03 = fma2(HV0, W1.y, a03); \
    a10 = fma2(HV1, W0.x, a10); a11 = fma2(HV1, W0.y, a11); \
    a12 = fma2(HV1, W1.x, a12); a13 = fma2(HV1, W1.y, a13); \
    a20 = fma2(HV2, W0.x, a20); a21 = fma2(HV2, W0.y, a21); \
    a22 = fma2(HV2, W1.x, a22); a23 = fma2(HV2, W1.y, a23); \
    a30 = fma2(HV3, W0.x, a30); a31 = fma2(HV3, W0.y, a31); \
    a32 = fma2(HV3, W1.x, a32); a33 = fma2(HV3, W1.y, a33); }

__global__ void __launch_bounds__(512, 1) lstm_layer_kernel(
    const float* __restrict__ xg,
    const float* __restrict__ WTI,
    float* __restrict__ hout,
    float* __restrict__ hlast)
{
    extern __shared__ float sm[];
    const ulonglong2* swA = (const ulonglong2*)sm;
    const ulonglong2* swB = swA + 6144;
    float* sh = sm + 49152;
    float4* sxf = (float4*)(sm + 49152 + 512);

    const int tid = threadIdx.x;
    const int j = tid & 127;
    const int u = tid >> 7;
    const int b0 = blockIdx.x * 4;

    {
        const float4* g4 = (const float4*)WTI;
        float4* s4 = (float4*)sm;
        #pragma unroll 4
        for (int i = tid; i < 6144; i += 512) s4[i] = g4[i];
        #pragma unroll 4
        for (int i = tid; i < 6144; i += 512) s4[6144 + i] = g4[8192 + i];
    }
    ulonglong2 wtA[4], wtB[4];
    {
        const ulonglong2* gA = (const ulonglong2*)WTI;
        const ulonglong2* gB = gA + 8192;
        int kt = KPSM + u * 4;
        #pragma unroll
        for (int i = 0; i < 4; i++) {
            wtA[i] = gA[(size_t)(kt + i) * 128 + j];
            wtB[i] = gB[(size_t)(kt + i) * 128 + j];
        }
    }
    sh[tid] = 0.0f;

    const int klo = u * 24;
    const int kplo = u * 12;

    const size_t xbase = ((size_t)(b0 + u)) * TT * GG + j;
    float* houtP = hout ? hout + ((size_t)(b0 + u)) * TT * HH + j : (float*)0;

    float xc0 = xg[xbase], xc1 = xg[xbase + 128], xc2 = xg[xbase + 256], xc3 = xg[xbase + 384];

    float cc = 0.0f, hh = 0.0f;
    __syncthreads();

    for (int t = 0; t < TT; t++) {
        ull a00 = 0, a01 = 0, a02 = 0, a03 = 0;
        ull a10 = 0, a11 = 0, a12 = 0, a13 = 0;
        ull a20 = 0, a21 = 0, a22 = 0, a23 = 0;
        ull a30 = 0, a31 = 0, a32 = 0, a33 = 0;

        float xn0 = 0, xn1 = 0, xn2 = 0, xn3 = 0;
        if (t + 1 < TT) {
            size_t o = xbase + (size_t)(t + 1) * GG;
            xn0 = xg[o]; xn1 = xg[o + 128]; xn2 = xg[o + 256]; xn3 = xg[o + 384];
        }

        #pragma unroll
        for (int g = 0; g < 6; g++) {
            int kb = klo + g * 4;
            ulonglong2 H0 = *(const ulonglong2*)(sh + kb);
            ulonglong2 H1 = *(const ulonglong2*)(sh + 128 + kb);
            ulonglong2 H2 = *(const ulonglong2*)(sh + 256 + kb);
            ulonglong2 H3 = *(const ulonglong2*)(sh + 384 + kb);
            int kpi = (kplo + g * 2) * 128 + j;
            ulonglong2 w0 = swA[kpi];
            ulonglong2 w1 = swB[kpi];
            MAC4(H0.x, H1.x, H2.x, H3.x, w0, w1);
            ulonglong2 w2 = swA[kpi + 128];
            ulonglong2 w3 = swB[kpi + 128];
            MAC4(H0.y, H1.y, H2.y, H3.y, w2, w3);
        }
        #pragma unroll
        for (int g = 0; g < 2; g++) {
            int kb = 96 + u * 8 + g * 4;
            ulonglong2 H0 = *(const ulonglong2*)(sh + kb);
            ulonglong2 H1 = *(const ulonglong2*)(sh + 128 + kb);
            ulonglong2 H2 = *(const ulonglong2*)(sh + 256 + kb);
            ulonglong2 H3 = *(const ulonglong2*)(sh + 384 + kb);
            MAC4(H0.x, H1.x, H2.x, H3.x, wtA[g * 2], wtB[g * 2]);
            MAC4(H0.y, H1.y, H2.y, H3.y, wtA[g * 2 + 1], wtB[g * 2 + 1]);
        }

        float4 s0, s1, s2, s3;
        s0.x = red2(a00); s0.y = red2(a01); s0.z = red2(a02); s0.w = red2(a03);
        s1.x = red2(a10); s1.y = red2(a11); s1.z = red2(a12); s1.w = red2(a13);
        s2.x = red2(a20); s2.y = red2(a21); s2.z = red2(a22); s2.w = red2(a23);
        s3.x = red2(a30); s3.y = red2(a31); s3.z = red2(a32); s3.w = red2(a33);

        if (u != 0) sxf[(0 * 3 + (u - 1)) * 128 + j] = s0;
        if (u != 1) sxf[(1 * 3 + ((u == 0) ? 0 : u - 1)) * 128 + j] = s1;
        if (u != 2) sxf[(2 * 3 + ((u == 3) ? 2 : u)) * 128 + j] = s2;
        if (u != 3) sxf[(3 * 3 + u) * 128 + j] = s3;
        __syncthreads();
        {
            float4 own = (u == 0) ? s0 : (u == 1) ? s1 : (u == 2) ? s2 : s3;
            float4 p0 = sxf[u * 384 + j];
            float4 p1 = sxf[u * 384 + 128 + j];
            float4 p2 = sxf[u * 384 + 256 + j];
            float gi = own.x + xc0 + p0.x + p1.x + p2.x;
            float gf = own.y + xc1 + p0.y + p1.y + p2.y;
            float gg2 = own.z + xc2 + p0.z + p1.z + p2.z;
            float go = own.w + xc3 + p0.w + p1.w + p2.w;

            float ii = sigf(gi), ff = sigf(gf), g = tanhx(gg2), oo = sigf(go);
            cc = ff * cc + ii * g;
            hh = oo * tanhx(cc);

            sh[u * 128 + j] = hh;
            if (hout) houtP[(size_t)t * HH] = hh;
        }
        xc0 = xn0; xc1 = xn1; xc2 = xn2; xc3 = xn3;
        __syncthreads();
    }

    if (hlast) hlast[(b0 + u) * HH + j] = hh;
}

// -------- MLP head (also zeroes the hidden_init tail: 512*256 = 131072 floats) --------
__device__ __forceinline__ float celuf(float x) { return x > 0.0f ? x : expm1f(x); }

__global__ void __launch_bounds__(256) head_kernel(
    const float* __restrict__ hlast,
    const float* __restrict__ W1, const float* __restrict__ b1,
    const float* __restrict__ W2, const float* __restrict__ b2,
    float* __restrict__ out, int tail_n)
{
    const int b = blockIdx.x;
    const int tid = threadIdx.x;
    __shared__ float sl[HH];
    __shared__ float sy[DLL];

    // zero one tail element per thread (grid*block == 512*256 == tail size)
    int zi = b * 256 + tid;
    if (zi < tail_n) out[BB * OUTD + zi] = 0.0f;

    if (tid < HH) sl[tid] = hlast[b * HH + tid];
    __syncthreads();

    float s = b1[tid];
    const float* w = W1 + (size_t)tid * HH;
    #pragma unroll 8
    for (int k = 0; k < HH; k++) s += sl[k] * w[k];
    sy[tid] = celuf(s);
    __syncthreads();

    if (tid < OUTD) {
        float s2 = b2[tid];
        const float* w2 = W2 + (size_t)tid * DLL;
        #pragma unroll 8
        for (int k = 0; k < DLL; k++) s2 += sy[k] * w2[k];
        out[b * OUTD + tid] = celuf(s2);
    }
}

__global__ void zero_extra(float* __restrict__ p, int n) {
    int i = blockIdx.x * 256 + threadIdx.x;
    if (i < n) p[i] = 0.0f;
}

// -------- launch --------
extern "C" void kernel_launch(void* const* d_in, const int* in_sizes, int n_in,
                              void* d_out, int out_size)
{
    const float* x    = (const float*)d_in[0];
    const float* Wih0 = (const float*)d_in[1];
    const float* Whh0 = (const float*)d_in[2];
    const float* bih0 = (const float*)d_in[3];
    const float* bhh0 = (const float*)d_in[4];
    const float* Wih1 = (const float*)d_in[5];
    const float* Whh1 = (const float*)d_in[6];
    const float* bih1 = (const float*)d_in[7];
    const float* bhh1 = (const float*)d_in[8];
    const float* W1   = (const float*)d_in[9];
    const float* b1   = (const float*)d_in[10];
    const float* W2   = (const float*)d_in[11];
    const float* b2   = (const float*)d_in[12];
    float* out = (float*)d_out;

    float *xgp, *h0p, *hlastp, *wt0p, *wt1p;
    __nv_bfloat16 *wimg0, *wimg1;
    cudaGetSymbolAddress((void**)&xgp,    g_xg);
    cudaGetSymbolAddress((void**)&h0p,    g_h0);
    cudaGetSymbolAddress((void**)&hlastp, g_hlast);
    cudaGetSymbolAddress((void**)&wt0p,   g_WT0);
    cudaGetSymbolAddress((void**)&wt1p,   g_WT1);
    cudaGetSymbolAddress((void**)&wimg0,  g_Wimg0);
    cudaGetSymbolAddress((void**)&wimg1,  g_Wimg1);

    const int smem_k128 = (2 * 128 * (HH + 8) + 2 * 64 * (HH + 8)) * 2 + 512 * 4;     // 106496
    const int smem_k32  = (2 * 128 * 40 + 8 * 128 * 40) * 2 + 512 * 4;                // 104448

    cudaFuncSetAttribute(lstm_layer_kernel, cudaFuncAttributeMaxDynamicSharedMemorySize, LSTM_SMEM);
    cudaFuncSetAttribute(mma_pregate,       cudaFuncAttributeMaxDynamicSharedMemorySize, smem_k128);
    cudaFuncSetAttribute(mma_pregate32,     cudaFuncAttributeMaxDynamicSharedMemorySize, smem_k32);

    prep_whh<<<256, 256>>>(Whh0, wt0p);
    prep_whh<<<256, 256>>>(Whh1, wt1p);
    prep_wsplit<<<(512 * INDIM + 255) / 256, 256>>>(Wih0, wimg0, INDIM);
    prep_wsplit<<<(512 * HH + 255) / 256, 256>>>(Wih1, wimg1, HH);

    // layer 0: pre-gates (K=32, all-W-resident, 1 barrier) then recurrence
    mma_pregate32<<<M_TOT / 128, 256, smem_k32>>>(x, wimg0, bih0, bhh0, xgp);
    lstm_layer_kernel<<<BB / 4, 512, LSTM_SMEM>>>(xgp, wt0p, h0p, nullptr);

    // layer 1: pre-gates (K=128) then recurrence
    mma_pregate<<<M_TOT / 128, 256, smem_k128>>>(h0p, wimg1, bih1, bhh1, xgp, HH);
    lstm_layer_kernel<<<BB / 4, 512, LSTM_SMEM>>>(xgp, wt1p, nullptr, hlastp);

    // head (+tail zeroing; covers exactly 512*256 elements)
    int tail = out_size - BB * OUTD;
    head_kernel<<<BB, 256>>>(hlastp, W1, b1, W2, b2, out, tail);
    int covered = BB * 256;
    if (tail > covered)
        zero_extra<<<(tail - covered + 255) / 256, 256>>>(out + BB * OUTD + covered, tail - covered);
}

// round 16
// speedup vs baseline: 1.7136x; 1.0032x over previous
#include <cuda_runtime.h>
#include <cuda_bf16.h>
#include <cstdint>
#include <cstddef>

typedef unsigned long long ull;

#define BB 512
#define TT 1024
#define INDIM 32
#define HH 128
#define GG 512            // 4*H
#define DLL 256
#define OUTD 32
#define M_TOT (BB*TT)     // 524288

// ---- lstm smem layout (round-4/7, proven — FROZEN) ----
#define KPSM 48
#define LSTM_SMEM ((49152 + 512 + 6144) * 4)    // 223232 bytes

// -------- device scratch (static; no runtime allocation) --------
__device__ float g_xg[(size_t)M_TOT * GG];
__device__ float g_h0[(size_t)M_TOT * HH];
__device__ float g_hlast[BB * HH];
__device__ float g_WT0[HH * GG];
__device__ float g_WT1[HH * GG];
// pre-split Wih images: [nb(8)][hi 64*stride | lo 64*stride] bf16, stride = K+8
__device__ __nv_bfloat16 g_Wimg0[8 * 128 * (INDIM + 8)];   // 80 KB
__device__ __nv_bfloat16 g_Wimg1[8 * 128 * (HH + 8)];      // 272 KB

// ---------------- f32x2 helpers (lstm) ----------------
__device__ __forceinline__ ull fma2(ull a, ull b, ull c) {
    ull d;
    asm("fma.rn.f32x2 %0, %1, %2, %3;" : "=l"(d) : "l"(a), "l"(b), "l"(c));
    return d;
}
__device__ __forceinline__ void unpack2(ull v, float& x, float& y) {
    unsigned a, b;
    asm("mov.b64 {%0, %1}, %2;" : "=r"(a), "=r"(b) : "l"(v));
    x = __uint_as_float(a);
    y = __uint_as_float(b);
}
__device__ __forceinline__ float red2(ull v) {
    float a, b;
    unpack2(v, a, b);
    return a + b;
}
__device__ __forceinline__ float sigf(float x)  { return __fdividef(1.0f, 1.0f + __expf(-x)); }
__device__ __forceinline__ float tanhx(float x) { return __fdividef(2.0f, 1.0f + __expf(-2.0f * x)) - 1.0f; }

// ---------------- ldmatrix helpers ----------------
__device__ __forceinline__ void ldsm_x4(uint32_t& r0, uint32_t& r1, uint32_t& r2, uint32_t& r3,
                                        uint32_t addr) {
    asm volatile("ldmatrix.sync.aligned.m8n8.x4.shared.b16 {%0,%1,%2,%3}, [%4];"
                 : "=r"(r0), "=r"(r1), "=r"(r2), "=r"(r3) : "r"(addr));
}
__device__ __forceinline__ void ldsm_x2(uint32_t& r0, uint32_t& r1, uint32_t addr) {
    asm volatile("ldmatrix.sync.aligned.m8n8.x2.shared.b16 {%0,%1}, [%2];"
                 : "=r"(r0), "=r"(r1) : "r"(addr));
}

// -------- interleave Whh for lstm (unchanged) --------
__global__ void prep_whh(const float* __restrict__ W, float* __restrict__ WTI) {
    int idx = blockIdx.x * 256 + threadIdx.x;
    if (idx < HH * GG) {
        int r = idx >> 15;
        int rem = idx & 32767;
        int kp = rem >> 9;
        int rem2 = rem & 511;
        int j = rem2 >> 2;
        int t = rem2 & 3;
        int qq = t >> 1;
        int e = t & 1;
        int q = r * 2 + qq;
        WTI[idx] = W[(q * HH + j) * HH + 2 * kp + e];
    }
}

// -------- pre-split Wih [512][K] into smem-image bf16 hi/lo blocks --------
__global__ void prep_wsplit(const float* __restrict__ W, __nv_bfloat16* __restrict__ img, int K) {
    int idx = blockIdx.x * 256 + threadIdx.x;
    if (idx < 512 * K) {
        int row = idx / K;
        int col = idx - row * K;
        int nb = row >> 6;
        int r = row & 63;
        int stride = K + 8;
        float v = W[idx];
        __nv_bfloat16 hi = __float2bfloat16(v);
        __nv_bfloat16 lo = __float2bfloat16(v - __bfloat162float(hi));
        size_t base = (size_t)nb * (128 * stride) + r * stride + col;
        img[base] = hi;
        img[base + 64 * stride] = lo;
    }
}

#define MMA_BF16(D, A0, A1, A2, A3, B0, B1) \
    asm volatile( \
        "mma.sync.aligned.m16n8k16.row.col.f32.bf16.bf16.f32 " \
        "{%0,%1,%2,%3}, {%4,%5,%6,%7}, {%8,%9}, {%0,%1,%2,%3};" \
        : "+f"((D)[0]), "+f"((D)[1]), "+f"((D)[2]), "+f"((D)[3]) \
        : "r"(A0), "r"(A1), "r"(A2), "r"(A3), "r"(B0), "r"(B1))

__device__ __forceinline__ void cvt_hilo(float4 v, uint2& oh, uint2& ol) {
    __nv_bfloat162 h01 = __floats2bfloat162_rn(v.x, v.y);
    __nv_bfloat162 h23 = __floats2bfloat162_rn(v.z, v.w);
    __nv_bfloat162 l01 = __floats2bfloat162_rn(v.x - __bfloat162float(h01.x),
                                               v.y - __bfloat162float(h01.y));
    __nv_bfloat162 l23 = __floats2bfloat162_rn(v.z - __bfloat162float(h23.x),
                                               v.w - __bfloat162float(h23.y));
    oh.x = *(uint32_t*)&h01; oh.y = *(uint32_t*)&h23;
    ol.x = *(uint32_t*)&l01; ol.y = *(uint32_t*)&l23;
}

// ================= K=128 pre-gate GEMM (ldmatrix fragment loads) =================
__global__ void __launch_bounds__(256, 2) mma_pregate(
    const float* __restrict__ A,              // [M][K] fp32
    const __nv_bfloat16* __restrict__ Wimg,   // pre-split hi/lo image
    const float* __restrict__ ba, const float* __restrict__ bb,
    float* __restrict__ C,                    // [M][512]
    int K)
{
    extern __shared__ __nv_bfloat16 smem[];
    const int stride = K + 8;
    __nv_bfloat16* sAhi = smem;
    __nv_bfloat16* sAlo = sAhi + 128 * stride;
    __nv_bfloat16* sWhi = sAlo + 128 * stride;
    __nv_bfloat16* sWlo = sWhi + 64 * stride;
    float* sbias = (float*)(sWlo + 64 * stride);

    const int tid = threadIdx.x;
    const int lane = tid & 31;
    const int wid = tid >> 5;
    const int wm = wid & 3;
    const int wn = wid >> 2;
    const int g = lane >> 2;
    const int tig = lane & 3;

    const int m0 = blockIdx.x * 128;
    const int kv = K >> 2;

    for (int i = tid; i < 512; i += 256) sbias[i] = ba[i] + bb[i];

    for (int idx = tid; idx < 128 * kv; idx += 256) {
        int row = idx / kv;
        int q = idx - row * kv;
        float4 v = *(const float4*)(A + (size_t)(m0 + row) * K + q * 4);
        uint2 oh, ol;
        cvt_hilo(v, oh, ol);
        *(uint2*)(&sAhi[row * stride + q * 4]) = oh;
        *(uint2*)(&sAlo[row * stride + q * 4]) = ol;
    }

    // ldmatrix lane-address components
    const uint32_t sAhi_b = (uint32_t)__cvta_generic_to_shared(sAhi);
    const uint32_t sWhi_b = (uint32_t)__cvta_generic_to_shared(sWhi);
    const uint32_t alo_off = (uint32_t)(128 * stride) * 2u;   // sAlo - sAhi bytes
    const uint32_t wlo_off = (uint32_t)(64 * stride) * 2u;    // sWlo - sWhi bytes
    const int arow = (lane & 7) + ((lane >> 3) & 1) * 8;      // 0..15
    const int acol = (lane >> 4) * 8;                         // 0 or 8
    const int brow = lane & 7;
    const int bcol = ((lane >> 3) & 1) * 8;

    const int wcpy = (128 * stride) / 8;

    for (int nb = 0; nb < 8; nb++) {
        __syncthreads();
        {
            const float4* src = (const float4*)(Wimg + (size_t)nb * (128 * stride));
            float4* dst = (float4*)sWhi;
            for (int i = tid; i < wcpy; i += 256) dst[i] = src[i];
        }
        __syncthreads();

        float d[2][4][4];
        #pragma unroll
        for (int mf = 0; mf < 2; mf++)
            #pragma unroll
            for (int nf = 0; nf < 4; nf++)
                #pragma unroll
                for (int e = 0; e < 4; e++) d[mf][nf][e] = 0.0f;

        const int nks = K >> 4;
        for (int ks = 0; ks < nks; ks++) {
            uint32_t AH[2][4], AL[2][4];
            #pragma unroll
            for (int mf = 0; mf < 2; mf++) {
                uint32_t a = sAhi_b +
                    ((uint32_t)((wm * 32 + mf * 16 + arow) * stride + ks * 16 + acol) << 1);
                ldsm_x4(AH[mf][0], AH[mf][1], AH[mf][2], AH[mf][3], a);
                ldsm_x4(AL[mf][0], AL[mf][1], AL[mf][2], AL[mf][3], a + alo_off);
            }
            #pragma unroll
            for (int nf = 0; nf < 4; nf++) {
                uint32_t b = sWhi_b +
                    ((uint32_t)((wn * 32 + nf * 8 + brow) * stride + ks * 16 + bcol) << 1);
                uint32_t BH0, BH1, BL0, BL1;
                ldsm_x2(BH0, BH1, b);
                ldsm_x2(BL0, BL1, b + wlo_off);
                #pragma unroll
                for (int mf = 0; mf < 2; mf++) {
                    MMA_BF16(d[mf][nf], AH[mf][0], AH[mf][1], AH[mf][2], AH[mf][3], BH0, BH1);
                    MMA_BF16(d[mf][nf], AL[mf][0], AL[mf][1], AL[mf][2], AL[mf][3], BH0, BH1);
                    MMA_BF16(d[mf][nf], AH[mf][0], AH[mf][1], AH[mf][2], AH[mf][3], BL0, BL1);
                }
            }
        }

        #pragma unroll
        for (int mf = 0; mf < 2; mf++) {
            int r0 = wm * 32 + mf * 16 + g;
            #pragma unroll
            for (int nf = 0; nf < 4; nf++) {
                int nl = nb * 64 + wn * 32 + nf * 8 + 2 * tig;
                float bx = sbias[nl];
                float by = sbias[nl + 1];
                float2 o0, o1;
                o0.x = d[mf][nf][0] + bx; o0.y = d[mf][nf][1] + by;
                o1.x = d[mf][nf][2] + bx; o1.y = d[mf][nf][3] + by;
                *(float2*)(C + (size_t)(m0 + r0) * GG + nl) = o0;
                *(float2*)(C + (size_t)(m0 + r0 + 8) * GG + nl) = o1;
            }
        }
    }
}

// ================= K=32 pre-gate GEMM: ALL W resident, one barrier, ldmatrix =================
__global__ void __launch_bounds__(256, 2) mma_pregate32(
    const float* __restrict__ A,              // [M][32] fp32
    const __nv_bfloat16* __restrict__ Wimg,   // pre-split hi/lo image (stride 40)
    const float* __restrict__ ba, const float* __restrict__ bb,
    float* __restrict__ C)                    // [M][512]
{
    constexpr int K = 32;
    constexpr int stride = 40;

    extern __shared__ __nv_bfloat16 smem[];
    __nv_bfloat16* sAhi = smem;                       // 128*40
    __nv_bfloat16* sAlo = sAhi + 128 * stride;        // 128*40
    __nv_bfloat16* sW   = sAlo + 128 * stride;        // 8*128*40
    float* sbias = (float*)(sW + 8 * 128 * stride);

    const int tid = threadIdx.x;
    const int lane = tid & 31;
    const int wid = tid >> 5;
    const int wm = wid & 3;
    const int wn = wid >> 2;
    const int g = lane >> 2;
    const int tig = lane & 3;

    const int m0 = blockIdx.x * 128;

    for (int i = tid; i < 512; i += 256) sbias[i] = ba[i] + bb[i];

    {
        const float4* src = (const float4*)Wimg;
        float4* dst = (float4*)sW;
        #pragma unroll
        for (int i = tid; i < 5120; i += 256) dst[i] = src[i];
    }
    #pragma unroll
    for (int it = 0; it < 4; it++) {
        int idx = tid + it * 256;
        int row = idx >> 3;
        int q = idx & 7;
        float4 v = *(const float4*)(A + (size_t)(m0 + row) * K + q * 4);
        uint2 oh, ol;
        cvt_hilo(v, oh, ol);
        *(uint2*)(&sAhi[row * stride + q * 4]) = oh;
        *(uint2*)(&sAlo[row * stride + q * 4]) = ol;
    }
    __syncthreads();   // the only barrier

    const uint32_t sAhi_b = (uint32_t)__cvta_generic_to_shared(sAhi);
    const uint32_t sW_b   = (uint32_t)__cvta_generic_to_shared(sW);
    const uint32_t alo_off = (uint32_t)(128 * stride) * 2u;
    const int arow = (lane & 7) + ((lane >> 3) & 1) * 8;
    const int acol = (lane >> 4) * 8;
    const int brow = lane & 7;
    const int bcol = ((lane >> 3) & 1) * 8;

    // preload A fragments once (shared across all nb)
    uint32_t AH[2][2][4], AL[2][2][4];   // [ks][mf][frag]
    #pragma unroll
    for (int ks = 0; ks < 2; ks++) {
        #pragma unroll
        for (int mf = 0; mf < 2; mf++) {
            uint32_t a = sAhi_b +
                ((uint32_t)((wm * 32 + mf * 16 + arow) * stride + ks * 16 + acol) << 1);
            ldsm_x4(AH[ks][mf][0], AH[ks][mf][1], AH[ks][mf][2], AH[ks][mf][3], a);
            ldsm_x4(AL[ks][mf][0], AL[ks][mf][1], AL[ks][mf][2], AL[ks][mf][3], a + alo_off);
        }
    }

    for (int nb = 0; nb < 8; nb++) {
        const uint32_t wbase = sW_b + (uint32_t)(nb * 128 * stride) * 2u;
        const uint32_t wlo_off = (uint32_t)(64 * stride) * 2u;

        float d[2][4][4];
        #pragma unroll
        for (int mf = 0; mf < 2; mf++)
            #pragma unroll
            for (int nf = 0; nf < 4; nf++)
                #pragma unroll
                for (int e = 0; e < 4; e++) d[mf][nf][e] = 0.0f;

        #pragma unroll
        for (int ks = 0; ks < 2; ks++) {
            #pragma unroll
            for (int nf = 0; nf < 4; nf++) {
                uint32_t b = wbase +
                    ((uint32_t)((wn * 32 + nf * 8 + brow) * stride + ks * 16 + bcol) << 1);
                uint32_t BH0, BH1, BL0, BL1;
                ldsm_x2(BH0, BH1, b);
                ldsm_x2(BL0, BL1, b + wlo_off);
                #pragma unroll
                for (int mf = 0; mf < 2; mf++) {
                    MMA_BF16(d[mf][nf], AH[ks][mf][0], AH[ks][mf][1], AH[ks][mf][2], AH[ks][mf][3], BH0, BH1);
                    MMA_BF16(d[mf][nf], AL[ks][mf][0], AL[ks][mf][1], AL[ks][mf][2], AL[ks][mf][3], BH0, BH1);
                    MMA_BF16(d[mf][nf], AH[ks][mf][0], AH[ks][mf][1], AH[ks][mf][2], AH[ks][mf][3], BL0, BL1);
                }
            }
        }

        #pragma unroll
        for (int mf = 0; mf < 2; mf++) {
            int r0 = wm * 32 + mf * 16 + g;
            #pragma unroll
            for (int nf = 0; nf < 4; nf++) {
                int nl = nb * 64 + wn * 32 + nf * 8 + 2 * tig;
                float bx = sbias[nl];
                float by = sbias[nl + 1];
                float2 o0, o1;
                o0.x = d[mf][nf][0] + bx; o0.y = d[mf][nf][1] + by;
                o1.x = d[mf][nf][2] + bx; o1.y = d[mf][nf][3] + by;
                *(float2*)(C + (size_t)(m0 + r0) * GG + nl) = o0;
                *(float2*)(C + (size_t)(m0 + r0 + 8) * GG + nl) = o1;
            }
        }
    }
}

// -------- LSTM recurrence (round-4/7, proven — FROZEN) --------
#define MAC4(HV0, HV1, HV2, HV3, W0, W1) { \
    a00 = fma2(HV0, W0.x, a00); a01 = fma2(HV0, W0.y, a01); \
    a02 = fma2(HV0, W1.x, a02); a03 = fma2(HV0, W1.y, a03); \
    a10 = fma2(HV1, W0.x, a10); a11 = fma2(HV1, W0.y, a11); \
    a12 = fma2(HV1, W1.x, a12); a13 = fma2(HV1, W1.y, a13); \
    a20 = fma2(HV2, W0.x, a20); a21 = fma2(HV2, W0.y, a21); \
    a22 = fma2(HV2, W1.x, a22); a23 = fma2(HV2, W1.y, a23); \
    a30 = fma2(HV3, W0.x, a30); a31 = fma2(HV3, W0.y, a31); \
    a32 = fma2(HV3, W1.x, a32); a33 = fma2(HV3, W1.y, a33); }

__global__ void __launch_bounds__(512, 1) lstm_layer_kernel(
    const float* __restrict__ xg,
    const float* __restrict__ WTI,
    float* __restrict__ hout,
    float* __restrict__ hlast)
{
    extern __shared__ float sm[];
    const ulonglong2* swA = (const ulonglong2*)sm;
    const ulonglong2* swB = swA + 6144;
    float* sh = sm + 49152;
    float4* sxf = (float4*)(sm + 49152 + 512);

    const int tid = threadIdx.x;
    const int j = tid & 127;
    const int u = tid >> 7;
    const int b0 = blockIdx.x * 4;

    {
        const float4* g4 = (const float4*)WTI;
        float4* s4 = (float4*)sm;
        #pragma unroll 4
        for (int i = tid; i < 6144; i += 512) s4[i] = g4[i];
        #pragma unroll 4
        for (int i = tid; i < 6144; i += 512) s4[6144 + i] = g4[8192 + i];
    }
    ulonglong2 wtA[4], wtB[4];
    {
        const ulonglong2* gA = (const ulonglong2*)WTI;
        const ulonglong2* gB = gA + 8192;
        int kt = KPSM + u * 4;
        #pragma unroll
        for (int i = 0; i < 4; i++) {
            wtA[i] = gA[(size_t)(kt + i) * 128 + j];
            wtB[i] = gB[(size_t)(kt + i) * 128 + j];
        }
    }
    sh[tid] = 0.0f;

    const int klo = u * 24;
    const int kplo = u * 12;

    const size_t xbase = ((size_t)(b0 + u)) * TT * GG + j;
    float* houtP = hout ? hout + ((size_t)(b0 + u)) * TT * HH + j : (float*)0;

    float xc0 = xg[xbase], xc1 = xg[xbase + 128], xc2 = xg[xbase + 256], xc3 = xg[xbase + 384];

    float cc = 0.0f, hh = 0.0f;
    __syncthreads();

    for (int t = 0; t < TT; t++) {
        ull a00 = 0, a01 = 0, a02 = 0, a03 = 0;
        ull a10 = 0, a11 = 0, a12 = 0, a13 = 0;
        ull a20 = 0, a21 = 0, a22 = 0, a23 = 0;
        ull a30 = 0, a31 = 0, a32 = 0, a33 = 0;

        float xn0 = 0, xn1 = 0, xn2 = 0, xn3 = 0;
        if (t + 1 < TT) {
            size_t o = xbase + (size_t)(t + 1) * GG;
            xn0 = xg[o]; xn1 = xg[o + 128]; xn2 = xg[o + 256]; xn3 = xg[o + 384];
        }

        #pragma unroll
        for (int g = 0; g < 6; g++) {
            int kb = klo + g * 4;
            ulonglong2 H0 = *(const ulonglong2*)(sh + kb);
            ulonglong2 H1 = *(const ulonglong2*)(sh + 128 + kb);
            ulonglong2 H2 = *(const ulonglong2*)(sh + 256 + kb);
            ulonglong2 H3 = *(const ulonglong2*)(sh + 384 + kb);
            int kpi = (kplo + g * 2) * 128 + j;
            ulonglong2 w0 = swA[kpi];
            ulonglong2 w1 = swB[kpi];
            MAC4(H0.x, H1.x, H2.x, H3.x, w0, w1);
            ulonglong2 w2 = swA[kpi + 128];
            ulonglong2 w3 = swB[kpi + 128];
            MAC4(H0.y, H1.y, H2.y, H3.y, w2, w3);
        }
        #pragma unroll
        for (int g = 0; g < 2; g++) {
            int kb = 96 + u * 8 + g * 4;
            ulonglong2 H0 = *(const ulonglong2*)(sh + kb);
            ulonglong2 H1 = *(const ulonglong2*)(sh + 128 + kb);
            ulonglong2 H2 = *(const ulonglong2*)(sh + 256 + kb);
            ulonglong2 H3 = *(const ulonglong2*)(sh + 384 + kb);
            MAC4(H0.x, H1.x, H2.x, H3.x, wtA[g * 2], wtB[g * 2]);
            MAC4(H0.y, H1.y, H2.y, H3.y, wtA[g * 2 + 1], wtB[g * 2 + 1]);
        }

        float4 s0, s1, s2, s3;
        s0.x = red2(a00); s0.y = red2(a01); s0.z = red2(a02); s0.w = red2(a03);
        s1.x = red2(a10); s1.y = red2(a11); s1.z = red2(a12); s1.w = red2(a13);
        s2.x = red2(a20); s2.y = red2(a21); s2.z = red2(a22); s2.w = red2(a23);
        s3.x = red2(a30); s3.y = red2(a31); s3.z = red2(a32); s3.w = red2(a33);

        if (u != 0) sxf[(0 * 3 + (u - 1)) * 128 + j] = s0;
        if (u != 1) sxf[(1 * 3 + ((u == 0) ? 0 : u - 1)) * 128 + j] = s1;
        if (u != 2) sxf[(2 * 3 + ((u == 3) ? 2 : u)) * 128 + j] = s2;
        if (u != 3) sxf[(3 * 3 + u) * 128 + j] = s3;
        __syncthreads();
        {
            float4 own = (u == 0) ? s0 : (u == 1) ? s1 : (u == 2) ? s2 : s3;
            float4 p0 = sxf[u * 384 + j];
            float4 p1 = sxf[u * 384 + 128 + j];
            float4 p2 = sxf[u * 384 + 256 + j];
            float gi = own.x + xc0 + p0.x + p1.x + p2.x;
            float gf = own.y + xc1 + p0.y + p1.y + p2.y;
            float gg2 = own.z + xc2 + p0.z + p1.z + p2.z;
            float go = own.w + xc3 + p0.w + p1.w + p2.w;

            float ii = sigf(gi), ff = sigf(gf), g = tanhx(gg2), oo = sigf(go);
            cc = ff * cc + ii * g;
            hh = oo * tanhx(cc);

            sh[u * 128 + j] = hh;
            if (hout) houtP[(size_t)t * HH] = hh;
        }
        xc0 = xn0; xc1 = xn1; xc2 = xn2; xc3 = xn3;
        __syncthreads();
    }

    if (hlast) hlast[(b0 + u) * HH + j] = hh;
}

// -------- MLP head (also zeroes the hidden_init tail) --------
__device__ __forceinline__ float celuf(float x) { return x > 0.0f ? x : expm1f(x); }

__global__ void __launch_bounds__(256) head_kernel(
    const float* __restrict__ hlast,
    const float* __restrict__ W1, const float* __restrict__ b1,
    const float* __restrict__ W2, const float* __restrict__ b2,
    float* __restrict__ out, int tail_n)
{
    const int b = blockIdx.x;
    const int tid = threadIdx.x;
    __shared__ float sl[HH];
    __shared__ float sy[DLL];

    int zi = b * 256 + tid;
    if (zi < tail_n) out[BB * OUTD + zi] = 0.0f;

    if (tid < HH) sl[tid] = hlast[b * HH + tid];
    __syncthreads();

    float s = b1[tid];
    const float* w = W1 + (size_t)tid * HH;
    #pragma unroll 8
    for (int k = 0; k < HH; k++) s += sl[k] * w[k];
    sy[tid] = celuf(s);
    __syncthreads();

    if (tid < OUTD) {
        float s2 = b2[tid];
        const float* w2 = W2 + (size_t)tid * DLL;
        #pragma unroll 8
        for (int k = 0; k < DLL; k++) s2 += sy[k] * w2[k];
        out[b * OUTD + tid] = celuf(s2);
    }
}

__global__ void zero_extra(float* __restrict__ p, int n) {
    int i = blockIdx.x * 256 + threadIdx.x;
    if (i < n) p[i] = 0.0f;
}

// -------- launch --------
extern "C" void kernel_launch(void* const* d_in, const int* in_sizes, int n_in,
                              void* d_out, int out_size)
{
    const float* x    = (const float*)d_in[0];
    const float* Wih0 = (const float*)d_in[1];
    const float* Whh0 = (const float*)d_in[2];
    const float* bih0 = (const float*)d_in[3];
    const float* bhh0 = (const float*)d_in[4];
    const float* Wih1 = (const float*)d_in[5];
    const float* Whh1 = (const float*)d_in[6];
    const float* bih1 = (const float*)d_in[7];
    const float* bhh1 = (const float*)d_in[8];
    const float* W1   = (const float*)d_in[9];
    const float* b1   = (const float*)d_in[10];
    const float* W2   = (const float*)d_in[11];
    const float* b2   = (const float*)d_in[12];
    float* out = (float*)d_out;

    float *xgp, *h0p, *hlastp, *wt0p, *wt1p;
    __nv_bfloat16 *wimg0, *wimg1;
    cudaGetSymbolAddress((void**)&xgp,    g_xg);
    cudaGetSymbolAddress((void**)&h0p,    g_h0);
    cudaGetSymbolAddress((void**)&hlastp, g_hlast);
    cudaGetSymbolAddress((void**)&wt0p,   g_WT0);
    cudaGetSymbolAddress((void**)&wt1p,   g_WT1);
    cudaGetSymbolAddress((void**)&wimg0,  g_Wimg0);
    cudaGetSymbolAddress((void**)&wimg1,  g_Wimg1);

    const int smem_k128 = (2 * 128 * (HH + 8) + 2 * 64 * (HH + 8)) * 2 + 512 * 4;     // 106496
    const int smem_k32  = (2 * 128 * 40 + 8 * 128 * 40) * 2 + 512 * 4;                // 104448

    cudaFuncSetAttribute(lstm_layer_kernel, cudaFuncAttributeMaxDynamicSharedMemorySize, LSTM_SMEM);
    cudaFuncSetAttribute(mma_pregate,       cudaFuncAttributeMaxDynamicSharedMemorySize, smem_k128);
    cudaFuncSetAttribute(mma_pregate32,     cudaFuncAttributeMaxDynamicSharedMemorySize, smem_k32);

    prep_whh<<<256, 256>>>(Whh0, wt0p);
    prep_whh<<<256, 256>>>(Whh1, wt1p);
    prep_wsplit<<<(512 * INDIM + 255) / 256, 256>>>(Wih0, wimg0, INDIM);
    prep_wsplit<<<(512 * HH + 255) / 256, 256>>>(Wih1, wimg1, HH);

    // layer 0: pre-gates (K=32, all-W-resident, 1 barrier, ldmatrix) then recurrence
    mma_pregate32<<<M_TOT / 128, 256, smem_k32>>>(x, wimg0, bih0, bhh0, xgp);
    lstm_layer_kernel<<<BB / 4, 512, LSTM_SMEM>>>(xgp, wt0p, h0p, nullptr);

    // layer 1: pre-gates (K=128, ldmatrix) then recurrence
    mma_pregate<<<M_TOT / 128, 256, smem_k128>>>(h0p, wimg1, bih1, bhh1, xgp, HH);
    lstm_layer_kernel<<<BB / 4, 512, LSTM_SMEM>>>(xgp, wt1p, nullptr, hlastp);

    // head (+tail zeroing; covers exactly 512*256 elements)
    int tail = out_size - BB * OUTD;
    head_kernel<<<BB, 256>>>(hlastp, W1, b1, W2, b2, out, tail);
    int covered = BB * 256;
    if (tail > covered)
        zero_extra<<<(tail - covered + 255) / 256, 256>>>(out + BB * OUTD + covered, tail - covered);
}